// round 2
// baseline (speedup 1.0000x reference)
#include <cuda_runtime.h>
#include <cuda_bf16.h>
#include <cstdint>

#define H 192
#define K2H 384
#define NNODES 504   // 256 leaves + 128 + 64 + 32 + 16 + 8

#define AS_STR 392   // padded k-stride (bf16 elems) -> conflict-free frag loads
#define PIPE_D 4     // cp.async pipeline depth
#define STAGE_ROWS 32
#define NSTAGES 12   // 384 rows / 32

// Scratch (allocation-free rule: __device__ globals)
__device__ __nv_bfloat16 g_Vbf[(size_t)H * K2H * K2H];   // 54 MB bf16 copy of Vt
__device__ float g_nodes[NNODES * H];                     // all node vectors, fp32

// ---------------------------------------------------------------------------
// cp.async helpers
// ---------------------------------------------------------------------------
__device__ __forceinline__ void cp16(void* smem, const void* gmem) {
    unsigned s = (unsigned)__cvta_generic_to_shared(smem);
    asm volatile("cp.async.cg.shared.global [%0], [%1], 16;\n" :: "r"(s), "l"(gmem));
}
__device__ __forceinline__ void cp_commit() {
    asm volatile("cp.async.commit_group;\n");
}
template <int N>
__device__ __forceinline__ void cp_wait() {
    asm volatile("cp.async.wait_group %0;\n" :: "n"(N));
}

// ---------------------------------------------------------------------------
// Kernel 1: convert Vt fp32 -> bf16 (exact trip count, high MLP)
// ---------------------------------------------------------------------------
__global__ void convert_kernel(const float* __restrict__ Vt) {
    // total float4 = 192*384*384/4 = 7,077,888 = 1728 * 256 * 16
    size_t t = (size_t)blockIdx.x * 256 + threadIdx.x;
    const float4* src = (const float4*)Vt;
    const size_t stride = 1728ull * 256ull;
    #pragma unroll 16
    for (int j = 0; j < 16; j++) {
        size_t i = t + stride * j;
        float4 v = src[i];
        __nv_bfloat162 lo, hi;
        lo.x = __float2bfloat16_rn(v.x); lo.y = __float2bfloat16_rn(v.y);
        hi.x = __float2bfloat16_rn(v.z); hi.y = __float2bfloat16_rn(v.w);
        uint2 pk;
        pk.x = *(const unsigned*)&lo;
        pk.y = *(const unsigned*)&hi;
        *(uint2*)(g_Vbf + 4 * i) = pk;
    }
}

// ---------------------------------------------------------------------------
// Kernel 2: leaf embedding gather
// ---------------------------------------------------------------------------
__global__ void leaf_kernel(const float* __restrict__ embed, const int* __restrict__ leaf_ids) {
    int n = blockIdx.x;          // 0..255
    int t = threadIdx.x;         // 0..191
    g_nodes[n * H + t] = embed[(size_t)leaf_ids[n] * H + t];
}

// ---------------------------------------------------------------------------
// bf16 m16n8k16 mma
// ---------------------------------------------------------------------------
__device__ __forceinline__ void mma16816(float* d, const unsigned* a, unsigned b0, unsigned b1) {
    asm volatile(
        "mma.sync.aligned.m16n8k16.row.col.f32.bf16.bf16.f32 "
        "{%0,%1,%2,%3},{%4,%5,%6,%7},{%8,%9},{%0,%1,%2,%3};"
        : "+f"(d[0]), "+f"(d[1]), "+f"(d[2]), "+f"(d[3])
        : "r"(a[0]), "r"(a[1]), "r"(a[2]), "r"(a[3]), "r"(b0), "r"(b1));
}

// ---------------------------------------------------------------------------
// Kernel 3: one tree level. blockIdx.x = h (192 CTAs), 256 threads.
// y[n] = tanh( c_n^T V_h c_n + (W c_n)_h + b_h )
// A = V_h streamed in 12 stages of 32 rows via depth-4 cp.async pipeline.
// B = node vectors c (k-major) resident in smem.
// Fused epilogue: y[n] += sum_x c[n,x] * U[x,n] per stage (deterministic).
// NT: n-tiles (of 8) per N-warp; Npad = 32*NT (2 M-warps x 4 N-warps).
// ---------------------------------------------------------------------------
template <int NT>
__global__ void __launch_bounds__(256, 1)
level_kernel(int prevBase, int prevN, int outBase, int Nlev,
             const float* __restrict__ W, const float* __restrict__ bias) {
    constexpr int Npad = 32 * NT;
    extern __shared__ char smraw[];
    __nv_bfloat16* As = (__nv_bfloat16*)smraw;              // [PIPE_D][32][AS_STR]
    __nv_bfloat16* Bs = As + PIPE_D * STAGE_ROWS * AS_STR;  // [Npad][AS_STR]
    float* ysm  = (float*)(Bs + Npad * AS_STR);             // [2][Npad]
    float* Wcol = ysm + 2 * Npad;                           // [384]

    const int h = blockIdx.x;
    const int tid = threadIdx.x;
    const __nv_bfloat16* __restrict__ Vh = g_Vbf + (size_t)h * K2H * K2H;

    // ---- prologue: start cp.async stages 0..PIPE_D-2 immediately ----
    #pragma unroll
    for (int s = 0; s < PIPE_D - 1; s++) {
        char* dst = (char*)(As + (s % PIPE_D) * STAGE_ROWS * AS_STR);
        const char* src = (const char*)(Vh + (size_t)s * STAGE_ROWS * K2H);
        #pragma unroll
        for (int j = 0; j < 6; j++) {                 // 1536 chunks of 16B / 256 thr
            int i = tid + 256 * j;
            int m = i / 48, kq = i - m * 48;
            cp16(dst + m * (AS_STR * 2) + kq * 16, src + m * (K2H * 2) + kq * 16);
        }
        cp_commit();
    }

    // ---- setup (overlaps with in-flight cp.async) ----
    for (int i = tid; i < 2 * Npad; i += 256) ysm[i] = 0.f;
    for (int y = tid; y < K2H; y += 256) Wcol[y] = W[y * H + h];

    // Gather B: Bs[n][y] = c[n,y] = concat(child_left, child_right)
    const int npt = Nlev >> 3;   // nodes per tree (B=8 trees)
    for (int i = tid; i < Npad * K2H; i += 256) {
        int n = i / K2H, y = i - n * K2H;
        float v = 0.f;
        if (n < Nlev) {
            int bt = n / npt, j = n - bt * npt;
            int child = prevBase + bt * prevN + 2 * j + (y >= H);
            v = g_nodes[child * H + (y >= H ? y - H : y)];
        }
        Bs[n * AS_STR + y] = __float2bfloat16_rn(v);
    }

    const int warp = tid >> 5, lane = tid & 31;
    const int wm = warp & 1, wn = warp >> 1;        // 2 M-warps x 4 N-warps
    const int g = lane >> 2, tg = lane & 3;
    const int m0 = wm * 16;
    const int nb0 = wn * (8 * NT);

    // ---- main pipelined loop over 12 stages ----
    for (int s = 0; s < NSTAGES; s++) {
        cp_wait<PIPE_D - 2>();
        __syncthreads();                            // stage s data + (iter0) Bs ready

        const __nv_bfloat16* A = As + (s % PIPE_D) * STAGE_ROWS * AS_STR;

        float acc[NT][4];
        #pragma unroll
        for (int nt = 0; nt < NT; nt++)
            #pragma unroll
            for (int q = 0; q < 4; q++) acc[nt][q] = 0.f;

        #pragma unroll 4
        for (int ks = 0; ks < 24; ks++) {           // K = 384
            int k0 = ks * 16;
            const __nv_bfloat16* Ar = A + (m0 + g) * AS_STR + k0 + 2 * tg;
            unsigned a[4];
            a[0] = *(const unsigned*)(Ar);
            a[1] = *(const unsigned*)(Ar + 8 * AS_STR);
            a[2] = *(const unsigned*)(Ar + 8);
            a[3] = *(const unsigned*)(Ar + 8 * AS_STR + 8);
            #pragma unroll
            for (int nt = 0; nt < NT; nt++) {
                const __nv_bfloat16* Br = Bs + (nb0 + nt * 8 + g) * AS_STR + k0 + 2 * tg;
                unsigned b0 = *(const unsigned*)(Br);
                unsigned b1 = *(const unsigned*)(Br + 8);
                mma16816(acc[nt], a, b0, b1);
            }
        }

        // fused epilogue: y[n] += sum over this stage's x rows of c[n,x]*U[x,n]
        #pragma unroll
        for (int nt = 0; nt < NT; nt++) {
            int na = nb0 + nt * 8 + 2 * tg;
            int x = s * STAGE_ROWS + m0 + g;
            float p0 = __bfloat162float(Bs[na * AS_STR + x])           * acc[nt][0]
                     + __bfloat162float(Bs[na * AS_STR + x + 8])       * acc[nt][2];
            float p1 = __bfloat162float(Bs[(na + 1) * AS_STR + x])     * acc[nt][1]
                     + __bfloat162float(Bs[(na + 1) * AS_STR + x + 8]) * acc[nt][3];
            #pragma unroll
            for (int sh = 4; sh < 32; sh <<= 1) {
                p0 += __shfl_xor_sync(0xffffffffu, p0, sh);
                p1 += __shfl_xor_sync(0xffffffffu, p1, sh);
            }
            if (g == 0) {                           // lanes 0..3 own 8 distinct n
                ysm[wm * Npad + na]     += p0;
                ysm[wm * Npad + na + 1] += p1;
            }
        }

        __syncthreads();                            // all warps done with buf (s+...)%D
        int sn = s + PIPE_D - 1;
        if (sn < NSTAGES) {
            char* dst = (char*)(As + (sn % PIPE_D) * STAGE_ROWS * AS_STR);
            const char* src = (const char*)(Vh + (size_t)sn * STAGE_ROWS * K2H);
            #pragma unroll
            for (int j = 0; j < 6; j++) {
                int i = tid + 256 * j;
                int m = i / 48, kq = i - m * 48;
                cp16(dst + m * (AS_STR * 2) + kq * 16, src + m * (K2H * 2) + kq * 16);
            }
            cp_commit();
        }
    }
    __syncthreads();

    // combine 2 warp-rows, add W-part + bias, tanh, write node column h
    for (int n = tid; n < Nlev; n += 256) {
        float xvx = ysm[n] + ysm[Npad + n];
        float wx = 0.f;
        #pragma unroll 4
        for (int y = 0; y < K2H; y++) wx += __bfloat162float(Bs[n * AS_STR + y]) * Wcol[y];
        g_nodes[(outBase + n) * H + h] = tanhf(xvx + wx + bias[h]);
    }
}

// ---------------------------------------------------------------------------
// Kernel 4: logits + log_softmax, one warp per node
// ---------------------------------------------------------------------------
__global__ void logits_kernel(const float* __restrict__ Wout_w,
                              const float* __restrict__ Wout_b,
                              float* __restrict__ out) {
    int node = (blockIdx.x * blockDim.x + threadIdx.x) >> 5;   // 63 * 8 = 504
    int lane = threadIdx.x & 31;
    const float* v = g_nodes + node * H;
    float l[5];
    #pragma unroll
    for (int o = 0; o < 5; o++) {
        float p = 0.f;
        #pragma unroll
        for (int i = 0; i < 6; i++) {
            int idx = lane + 32 * i;
            p += v[idx] * Wout_w[o * H + idx];
        }
        #pragma unroll
        for (int s = 16; s; s >>= 1) p += __shfl_xor_sync(0xffffffffu, p, s);
        l[o] = p + Wout_b[o];
    }
    if (lane == 0) {
        float m = l[0];
        #pragma unroll
        for (int o = 1; o < 5; o++) m = fmaxf(m, l[o]);
        float s = 0.f;
        #pragma unroll
        for (int o = 0; o < 5; o++) s += expf(l[o] - m);
        float ls = logf(s);
        #pragma unroll
        for (int o = 0; o < 5; o++) out[node * 5 + o] = l[o] - m - ls;
    }
}

// ---------------------------------------------------------------------------
static inline size_t smem_bytes(int NT) {
    int Npad = 32 * NT;
    return (size_t)(PIPE_D * STAGE_ROWS + Npad) * AS_STR * 2 + (2 * Npad + K2H) * 4;
}

extern "C" void kernel_launch(void* const* d_in, const int* in_sizes, int n_in,
                              void* d_out, int out_size) {
    const float* embed  = (const float*)d_in[0];
    const float* Vt     = (const float*)d_in[1];
    const float* W      = (const float*)d_in[2];
    const float* b      = (const float*)d_in[3];
    const float* Wout_w = (const float*)d_in[4];
    const float* Wout_b = (const float*)d_in[5];
    const int*   leaf   = (const int*)d_in[6];
    float* out = (float*)d_out;

    static bool attr_set = false;
    if (!attr_set) {
        cudaFuncSetAttribute(level_kernel<4>, cudaFuncAttributeMaxDynamicSharedMemorySize, (int)smem_bytes(4));
        cudaFuncSetAttribute(level_kernel<2>, cudaFuncAttributeMaxDynamicSharedMemorySize, (int)smem_bytes(2));
        cudaFuncSetAttribute(level_kernel<1>, cudaFuncAttributeMaxDynamicSharedMemorySize, (int)smem_bytes(1));
        attr_set = true;
    }

    convert_kernel<<<1728, 256>>>(Vt);
    leaf_kernel<<<256, H>>>(embed, leaf);

    //                                   prevBase prevN outBase N
    level_kernel<4><<<192, 256, smem_bytes(4)>>>(0,   32, 256, 128, W, b);
    level_kernel<2><<<192, 256, smem_bytes(2)>>>(256, 16, 384,  64, W, b);
    level_kernel<1><<<192, 256, smem_bytes(1)>>>(384,  8, 448,  32, W, b);
    level_kernel<1><<<192, 256, smem_bytes(1)>>>(448,  4, 480,  16, W, b);
    level_kernel<1><<<192, 256, smem_bytes(1)>>>(480,  2, 496,   8, W, b);

    logits_kernel<<<63, 256>>>(Wout_w, Wout_b, out);
}

// round 5
// speedup vs baseline: 2.5714x; 2.5714x over previous
#include <cuda_runtime.h>
#include <cuda_bf16.h>
#include <cstdint>

#define H 192
#define X384 384
#define NNODES 504   // 256 leaves + 128 + 64 + 32 + 16 + 8

#define AP 72        // A stage row stride (bf16 elems): 64 + 8 pad
#define BP 392       // B row stride (bf16 elems): 384 + 8 pad
#define KSUB 64      // k sub-chunk
#define NSUB 6       // 384 / 64

// Scratch (allocation-free rule: __device__ globals)
__device__ __nv_bfloat16 g_Vbf[(size_t)H * X384 * X384];  // 54 MB bf16 V
__device__ __nv_bfloat16 g_WTbf[256 * X384];              // W^T bf16, rows 192..255 stay zero
__device__ float g_nodes[NNODES * H];
__device__ float g_part[4][H][128];                        // 3 x-block partials + Wx

// ---------------------------------------------------------------------------
// async-copy / ldmatrix helpers
// ---------------------------------------------------------------------------
__device__ __forceinline__ void cp16(void* smem, const void* gmem) {
    unsigned s = (unsigned)__cvta_generic_to_shared(smem);
    asm volatile("cp.async.cg.shared.global [%0], [%1], 16;\n" :: "r"(s), "l"(gmem));
}
__device__ __forceinline__ void cp_commit() { asm volatile("cp.async.commit_group;\n"); }
template <int N>
__device__ __forceinline__ void cp_wait() { asm volatile("cp.async.wait_group %0;\n" :: "n"(N)); }

__device__ __forceinline__ void ldmx4(unsigned* a, unsigned saddr) {
    asm volatile("ldmatrix.sync.aligned.m8n8.x4.shared.b16 {%0,%1,%2,%3}, [%4];"
                 : "=r"(a[0]), "=r"(a[1]), "=r"(a[2]), "=r"(a[3]) : "r"(saddr));
}
__device__ __forceinline__ void mma16816(float* d, const unsigned* a, unsigned b0, unsigned b1) {
    asm volatile(
        "mma.sync.aligned.m16n8k16.row.col.f32.bf16.bf16.f32 "
        "{%0,%1,%2,%3},{%4,%5,%6,%7},{%8,%9},{%0,%1,%2,%3};"
        : "+f"(d[0]), "+f"(d[1]), "+f"(d[2]), "+f"(d[3])
        : "r"(a[0]), "r"(a[1]), "r"(a[2]), "r"(a[3]), "r"(b0), "r"(b1));
}

// ---------------------------------------------------------------------------
// Kernel 1: convert Vt fp32 -> bf16
// ---------------------------------------------------------------------------
__global__ void convert_kernel(const float* __restrict__ Vt) {
    size_t t = (size_t)blockIdx.x * 256 + threadIdx.x;
    const float4* src = (const float4*)Vt;
    const size_t stride = 1728ull * 256ull;
    #pragma unroll 16
    for (int j = 0; j < 16; j++) {
        size_t i = t + stride * j;
        float4 v = src[i];
        __nv_bfloat162 lo, hi;
        lo.x = __float2bfloat16_rn(v.x); lo.y = __float2bfloat16_rn(v.y);
        hi.x = __float2bfloat16_rn(v.z); hi.y = __float2bfloat16_rn(v.w);
        uint2 pk; pk.x = *(const unsigned*)&lo; pk.y = *(const unsigned*)&hi;
        *(uint2*)(g_Vbf + 4 * i) = pk;
    }
}

// W^T bf16: g_WTbf[h][y] = W[y][h]
__global__ void convertWT_kernel(const float* __restrict__ W) {
    int h = blockIdx.x;
    for (int y = threadIdx.x; y < X384; y += blockDim.x)
        g_WTbf[h * X384 + y] = __float2bfloat16_rn(W[y * H + h]);
}

// ---------------------------------------------------------------------------
// Kernel 2: leaf embedding gather
// ---------------------------------------------------------------------------
__global__ void leaf_kernel(const float* __restrict__ embed, const int* __restrict__ leaf_ids) {
    int n = blockIdx.x, t = threadIdx.x;
    g_nodes[n * H + t] = embed[(size_t)leaf_ids[n] * H + t];
}

// ---------------------------------------------------------------------------
// Main GEMM per level.
//   mblk < 576 : A = V rows (h = mblk/3, x-block = mblk%3), epilogue reduces
//                over x with weight c[n,x] (read from the same B tile) ->
//                g_part[xblk][h][n].
//   mblk 576/7 : A = W^T rows, accumulators ARE Wx -> g_part[3][h][n].
// grid = (578, Nlev/NTILE), 256 threads.
// ---------------------------------------------------------------------------
template <int NTILE>
__global__ void __launch_bounds__(256)
gemm_level(int prevBase, int prevN, int Nlev) {
    constexpr int NWN = (NTILE > 8) ? 2 : 1;     // n-warp columns
    constexpr int NWM = 8 / NWN;                 // m-warp rows
    constexpr int MT  = 128 / (NWM * 16);        // m16 tiles per warp (2 or 1)
    constexpr int NT  = (NTILE / NWN) / 8;       // n8 tiles per warp

    extern __shared__ char smraw[];
    __nv_bfloat16* As = (__nv_bfloat16*)smraw;         // [3][128][AP]
    __nv_bfloat16* Bs = As + 3 * 128 * AP;             // [NTILE][BP]
    float* ysm = (float*)(Bs + NTILE * BP);            // [NWM][NTILE]

    const int mblk = blockIdx.x;
    const int n0 = blockIdx.y * NTILE;
    const bool isW = (mblk >= 576);
    const __nv_bfloat16* __restrict__ Abase = isW
        ? (g_WTbf + (size_t)(mblk - 576) * 128 * X384)
        : (g_Vbf + ((size_t)(mblk / 3) * X384 + (mblk % 3) * 128) * X384);

    const int tid = threadIdx.x;
    // cp.async mapping: stage = 128 rows x 8 chunks of 16B = 1024 chunks,
    // 256 threads x 4 chunks. row8 covers 32 rows per strip, ch8 all 8 columns.
    const int row8 = tid >> 3, ch8 = tid & 7;

    // prologue: stages 0,1
    #pragma unroll
    for (int s = 0; s < 2; s++) {
        const char* src = (const char*)Abase + s * KSUB * 2;
        char* dst = (char*)(As + s * 128 * AP);
        #pragma unroll
        for (int t = 0; t < 4; t++) {
            int r = row8 + t * 32;
            cp16(dst + r * (AP * 2) + ch8 * 16, src + (size_t)r * (X384 * 2) + ch8 * 16);
        }
        cp_commit();
    }

    // B gather: Bs[n][y] = c[n0+n, y] = concat(childL, childR), fp32 -> bf16
    const int npt = Nlev >> 3;
    for (int i = tid; i < NTILE * 96; i += 256) {
        int n = i / 96, q = i - n * 96;
        int half = q / 48, yl = (q - half * 48) * 4;
        int ng = n0 + n;
        int bt = ng / npt, j = ng - bt * npt;
        int child = prevBase + bt * prevN + 2 * j + half;
        float4 v = *(const float4*)(g_nodes + (size_t)child * H + yl);
        __nv_bfloat162 lo, hi;
        lo.x = __float2bfloat16_rn(v.x); lo.y = __float2bfloat16_rn(v.y);
        hi.x = __float2bfloat16_rn(v.z); hi.y = __float2bfloat16_rn(v.w);
        uint2 pk; pk.x = *(const unsigned*)&lo; pk.y = *(const unsigned*)&hi;
        *(uint2*)(Bs + n * BP + half * H + yl) = pk;
    }

    const int warp = tid >> 5, lane = tid & 31;
    const int wm = warp % NWM, wn = warp / NWM;
    const int g = lane >> 2, tg = lane & 3;
    const int m0 = wm * (MT * 16);
    const int nb0 = wn * (NT * 8);
    const int lrow = lane & 15;
    const int lcol = (lane >> 4) * 8;

    const unsigned As_u = (unsigned)__cvta_generic_to_shared(As);

    float acc[MT][NT][4];
    #pragma unroll
    for (int mt = 0; mt < MT; mt++)
        #pragma unroll
        for (int nt = 0; nt < NT; nt++)
            #pragma unroll
            for (int q = 0; q < 4; q++) acc[mt][nt][q] = 0.f;

    for (int s = 0; s < NSUB; s++) {
        cp_wait<1>();
        __syncthreads();
        // refill the buffer freed by stage s-1 before computing
        if (s + 2 < NSUB) {
            const char* src = (const char*)Abase + (s + 2) * KSUB * 2;
            char* dst = (char*)(As + ((s + 2) % 3) * 128 * AP);
            #pragma unroll
            for (int t = 0; t < 4; t++) {
                int r = row8 + t * 32;
                cp16(dst + r * (AP * 2) + ch8 * 16, src + (size_t)r * (X384 * 2) + ch8 * 16);
            }
        }
        cp_commit();   // may be empty at tail; keeps group accounting simple

        const unsigned stg = As_u + (s % 3) * (128 * AP * 2);
        const __nv_bfloat16* Bk = Bs + s * KSUB;

        #pragma unroll
        for (int ks = 0; ks < 4; ks++) {
            int k0 = ks * 16;
            unsigned a[MT][4];
            #pragma unroll
            for (int mt = 0; mt < MT; mt++)
                ldmx4(a[mt], stg + ((m0 + mt * 16 + lrow) * AP + k0 + lcol) * 2);
            #pragma unroll
            for (int nt = 0; nt < NT; nt++) {
                const __nv_bfloat16* Br = Bk + (nb0 + nt * 8 + g) * BP + k0 + 2 * tg;
                unsigned b0 = *(const unsigned*)(Br);
                unsigned b1 = *(const unsigned*)(Br + 8);
                #pragma unroll
                for (int mt = 0; mt < MT; mt++) mma16816(acc[mt][nt], a[mt], b0, b1);
            }
        }
    }

    if (!isW) {
        const int xb = mblk % 3, hh = mblk / 3;
        #pragma unroll
        for (int nt = 0; nt < NT; nt++) {
            int nl = nb0 + nt * 8 + 2 * tg;            // local n (Bs row)
            float p0 = 0.f, p1 = 0.f;
            #pragma unroll
            for (int mt = 0; mt < MT; mt++) {
                int xf = xb * 128 + m0 + mt * 16 + g;  // global x for c[n,x]
                float c0 = __bfloat162float(Bs[nl * BP + xf]);
                float c1 = __bfloat162float(Bs[nl * BP + xf + 8]);
                float d0 = __bfloat162float(Bs[(nl + 1) * BP + xf]);
                float d1 = __bfloat162float(Bs[(nl + 1) * BP + xf + 8]);
                p0 += c0 * acc[mt][nt][0] + c1 * acc[mt][nt][2];
                p1 += d0 * acc[mt][nt][1] + d1 * acc[mt][nt][3];
            }
            #pragma unroll
            for (int sh = 4; sh < 32; sh <<= 1) {      // reduce over g
                p0 += __shfl_xor_sync(0xffffffffu, p0, sh);
                p1 += __shfl_xor_sync(0xffffffffu, p1, sh);
            }
            if (g == 0) {
                ysm[wm * NTILE + nl] = p0;
                ysm[wm * NTILE + nl + 1] = p1;
            }
        }
        __syncthreads();
        for (int n = tid; n < NTILE; n += 256) {
            float v = 0.f;
            #pragma unroll
            for (int w = 0; w < NWM; w++) v += ysm[w * NTILE + n];
            g_part[xb][hh][n0 + n] = v;
        }
    } else {
        const int hb = (mblk - 576) * 128;
        #pragma unroll
        for (int mt = 0; mt < MT; mt++) {
            int hh = hb + m0 + mt * 16 + g;
            #pragma unroll
            for (int nt = 0; nt < NT; nt++) {
                int n = n0 + nb0 + nt * 8 + 2 * tg;
                if (hh < H) {
                    g_part[3][hh][n]     = acc[mt][nt][0];
                    g_part[3][hh][n + 1] = acc[mt][nt][1];
                }
                if (hh + 8 < H) {
                    g_part[3][hh + 8][n]     = acc[mt][nt][2];
                    g_part[3][hh + 8][n + 1] = acc[mt][nt][3];
                }
            }
        }
    }
}

// ---------------------------------------------------------------------------
// Finalize: sum partials + bias, tanh, scatter to node storage
// ---------------------------------------------------------------------------
__global__ void finalize_kernel(int outBase, const float* __restrict__ bias) {
    int n = blockIdx.x, h = threadIdx.x;
    float v = g_part[0][h][n] + g_part[1][h][n] + g_part[2][h][n]
            + g_part[3][h][n] + bias[h];
    g_nodes[(size_t)(outBase + n) * H + h] = tanhf(v);
}

// ---------------------------------------------------------------------------
// Logits + log_softmax, one warp per node
// ---------------------------------------------------------------------------
__global__ void logits_kernel(const float* __restrict__ Wout_w,
                              const float* __restrict__ Wout_b,
                              float* __restrict__ out) {
    int node = (blockIdx.x * blockDim.x + threadIdx.x) >> 5;   // 63 * 8 = 504
    int lane = threadIdx.x & 31;
    const float* v = g_nodes + (size_t)node * H;
    float l[5];
    #pragma unroll
    for (int o = 0; o < 5; o++) {
        float p = 0.f;
        #pragma unroll
        for (int i = 0; i < 6; i++) {
            int idx = lane + 32 * i;
            p += v[idx] * Wout_w[o * H + idx];
        }
        #pragma unroll
        for (int s = 16; s; s >>= 1) p += __shfl_xor_sync(0xffffffffu, p, s);
        l[o] = p + Wout_b[o];
    }
    if (lane == 0) {
        float m = l[0];
        #pragma unroll
        for (int o = 1; o < 5; o++) m = fmaxf(m, l[o]);
        float s = 0.f;
        #pragma unroll
        for (int o = 0; o < 5; o++) s += expf(l[o] - m);
        float ls = logf(s);
        #pragma unroll
        for (int o = 0; o < 5; o++) out[node * 5 + o] = l[o] - m - ls;
    }
}

// ---------------------------------------------------------------------------
static inline size_t smem_bytes(int NTILE) {
    int NWM = (NTILE > 8) ? 4 : 8;
    return (size_t)3 * 128 * AP * 2 + (size_t)NTILE * BP * 2 + (size_t)NWM * NTILE * 4;
}

extern "C" void kernel_launch(void* const* d_in, const int* in_sizes, int n_in,
                              void* d_out, int out_size) {
    const float* embed  = (const float*)d_in[0];
    const float* Vt     = (const float*)d_in[1];
    const float* W      = (const float*)d_in[2];
    const float* b      = (const float*)d_in[3];
    const float* Wout_w = (const float*)d_in[4];
    const float* Wout_b = (const float*)d_in[5];
    const int*   leaf   = (const int*)d_in[6];
    float* out = (float*)d_out;

    static bool attr_set = false;
    if (!attr_set) {
        cudaFuncSetAttribute(gemm_level<64>, cudaFuncAttributeMaxDynamicSharedMemorySize, (int)smem_bytes(64));
        cudaFuncSetAttribute(gemm_level<32>, cudaFuncAttributeMaxDynamicSharedMemorySize, (int)smem_bytes(32));
        cudaFuncSetAttribute(gemm_level<16>, cudaFuncAttributeMaxDynamicSharedMemorySize, (int)smem_bytes(16));
        cudaFuncSetAttribute(gemm_level<8>,  cudaFuncAttributeMaxDynamicSharedMemorySize, (int)smem_bytes(8));
        attr_set = true;
    }

    convert_kernel<<<1728, 256>>>(Vt);
    convertWT_kernel<<<192, 128>>>(W);
    leaf_kernel<<<256, H>>>(embed, leaf);

    // level 0: 256 leaves -> 128 nodes
    gemm_level<64><<<dim3(578, 2), 256, smem_bytes(64)>>>(0, 32, 128);
    finalize_kernel<<<128, H>>>(256, b);
    // level 1: 128 -> 64
    gemm_level<64><<<dim3(578, 1), 256, smem_bytes(64)>>>(256, 16, 64);
    finalize_kernel<<<64, H>>>(384, b);
    // level 2: 64 -> 32
    gemm_level<32><<<dim3(578, 1), 256, smem_bytes(32)>>>(384, 8, 32);
    finalize_kernel<<<32, H>>>(448, b);
    // level 3: 32 -> 16
    gemm_level<16><<<dim3(578, 1), 256, smem_bytes(16)>>>(448, 4, 16);
    finalize_kernel<<<16, H>>>(480, b);
    // level 4: 16 -> 8
    gemm_level<8><<<dim3(578, 1), 256, smem_bytes(8)>>>(480, 2, 8);
    finalize_kernel<<<8, H>>>(496, b);

    logits_kernel<<<63, 256>>>(Wout_w, Wout_b, out);
}

// round 7
// speedup vs baseline: 2.6194x; 1.0187x over previous
#include <cuda_runtime.h>
#include <cuda_bf16.h>
#include <cstdint>

#define H 192
#define X384 384
#define NNODES 504   // 256 leaves + 128 + 64 + 32 + 16 + 8

#define AP 72        // A stage row stride (bf16 elems): 64 + 8 pad
#define BP 392       // B row stride (bf16 elems): 384 + 8 pad
#define KSUB 64      // k sub-chunk
#define NSUB 6       // 384 / 64

// Scratch (allocation-free rule: __device__ globals)
__device__ __nv_bfloat16 g_Vbf[(size_t)H * X384 * X384];  // 54 MB bf16 V
__device__ __nv_bfloat16 g_WTbf[256 * X384];              // W^T bf16, rows 192..255 stay zero
__device__ float g_nodes[NNODES * H];
__device__ float g_part[4][H][128];                        // 3 x-block partials + Wx

// ---------------------------------------------------------------------------
// async-copy / ldmatrix helpers
// ---------------------------------------------------------------------------
__device__ __forceinline__ void cp16(void* smem, const void* gmem) {
    unsigned s = (unsigned)__cvta_generic_to_shared(smem);
    asm volatile("cp.async.cg.shared.global [%0], [%1], 16;\n" :: "r"(s), "l"(gmem));
}
__device__ __forceinline__ void cp_commit() { asm volatile("cp.async.commit_group;\n"); }
template <int N>
__device__ __forceinline__ void cp_wait() { asm volatile("cp.async.wait_group %0;\n" :: "n"(N)); }

__device__ __forceinline__ void ldmx4(unsigned* a, unsigned saddr) {
    asm volatile("ldmatrix.sync.aligned.m8n8.x4.shared.b16 {%0,%1,%2,%3}, [%4];"
                 : "=r"(a[0]), "=r"(a[1]), "=r"(a[2]), "=r"(a[3]) : "r"(saddr));
}
__device__ __forceinline__ void ldmx2(unsigned* a, unsigned saddr) {
    asm volatile("ldmatrix.sync.aligned.m8n8.x2.shared.b16 {%0,%1}, [%2];"
                 : "=r"(a[0]), "=r"(a[1]) : "r"(saddr));
}
__device__ __forceinline__ void mma16816(float* d, const unsigned* a, unsigned b0, unsigned b1) {
    asm volatile(
        "mma.sync.aligned.m16n8k16.row.col.f32.bf16.bf16.f32 "
        "{%0,%1,%2,%3},{%4,%5,%6,%7},{%8,%9},{%0,%1,%2,%3};"
        : "+f"(d[0]), "+f"(d[1]), "+f"(d[2]), "+f"(d[3])
        : "r"(a[0]), "r"(a[1]), "r"(a[2]), "r"(a[3]), "r"(b0), "r"(b1));
}

// ---------------------------------------------------------------------------
// Kernel 1: convert Vt fp32 -> bf16
// ---------------------------------------------------------------------------
__global__ void convert_kernel(const float* __restrict__ Vt) {
    size_t t = (size_t)blockIdx.x * 256 + threadIdx.x;
    const float4* src = (const float4*)Vt;
    const size_t stride = 1728ull * 256ull;
    #pragma unroll 16
    for (int j = 0; j < 16; j++) {
        size_t i = t + stride * j;
        float4 v = src[i];
        __nv_bfloat162 lo, hi;
        lo.x = __float2bfloat16_rn(v.x); lo.y = __float2bfloat16_rn(v.y);
        hi.x = __float2bfloat16_rn(v.z); hi.y = __float2bfloat16_rn(v.w);
        uint2 pk; pk.x = *(const unsigned*)&lo; pk.y = *(const unsigned*)&hi;
        *(uint2*)(g_Vbf + 4 * i) = pk;
    }
}

// W^T bf16: g_WTbf[h][y] = W[y][h]
__global__ void convertWT_kernel(const float* __restrict__ W) {
    int h = blockIdx.x;
    for (int y = threadIdx.x; y < X384; y += blockDim.x)
        g_WTbf[h * X384 + y] = __float2bfloat16_rn(W[y * H + h]);
}

// ---------------------------------------------------------------------------
// Kernel 2: leaf embedding gather
// ---------------------------------------------------------------------------
__global__ void leaf_kernel(const float* __restrict__ embed, const int* __restrict__ leaf_ids) {
    int n = blockIdx.x, t = threadIdx.x;
    g_nodes[n * H + t] = embed[(size_t)leaf_ids[n] * H + t];
}

// ---------------------------------------------------------------------------
// Main GEMM per level (see R3/R4 notes). ldmatrix-fed A and B operands.
// grid = (578, Nlev/NTILE), 256 threads.
// ---------------------------------------------------------------------------
template <int NTILE>
__global__ void __launch_bounds__(256)
gemm_level(int prevBase, int prevN, int Nlev) {
    constexpr int NWN = (NTILE > 8) ? 2 : 1;     // n-warp columns
    constexpr int NWM = 8 / NWN;                 // m-warp rows
    constexpr int MT  = 128 / (NWM * 16);        // m16 tiles per warp (2 or 1)
    constexpr int NT  = (NTILE / NWN) / 8;       // n8 tiles per warp
    constexpr int NP  = NT / 2;                  // ldmatrix.x4 pairs (0 when NT==1)

    extern __shared__ char smraw[];
    __nv_bfloat16* As = (__nv_bfloat16*)smraw;         // [3][128][AP]
    __nv_bfloat16* Bs = As + 3 * 128 * AP;             // [NTILE][BP]
    float* ysm = (float*)(Bs + NTILE * BP);            // [NWM][NTILE]

    const int mblk = blockIdx.x;
    const int n0 = blockIdx.y * NTILE;
    const bool isW = (mblk >= 576);
    const __nv_bfloat16* __restrict__ Abase = isW
        ? (g_WTbf + (size_t)(mblk - 576) * 128 * X384)
        : (g_Vbf + ((size_t)(mblk / 3) * X384 + (mblk % 3) * 128) * X384);

    const int tid = threadIdx.x;
    const int row8 = tid >> 3, ch8 = tid & 7;          // 256 thr x 4 chunks = 1024 chunks/stage

    // prologue: stages 0,1
    #pragma unroll
    for (int s = 0; s < 2; s++) {
        const char* src = (const char*)Abase + s * KSUB * 2;
        char* dst = (char*)(As + s * 128 * AP);
        #pragma unroll
        for (int t = 0; t < 4; t++) {
            int r = row8 + t * 32;
            cp16(dst + r * (AP * 2) + ch8 * 16, src + (size_t)r * (X384 * 2) + ch8 * 16);
        }
        cp_commit();
    }

    // B gather: Bs[n][y] = c[n0+n, y] = concat(childL, childR), fp32 -> bf16
    const int npt = Nlev >> 3;
    for (int i = tid; i < NTILE * 96; i += 256) {
        int n = i / 96, q = i - n * 96;
        int half = q / 48, yl = (q - half * 48) * 4;
        int ng = n0 + n;
        int bt = ng / npt, j = ng - bt * npt;
        int child = prevBase + bt * prevN + 2 * j + half;
        float4 v = *(const float4*)(g_nodes + (size_t)child * H + yl);
        __nv_bfloat162 lo, hi;
        lo.x = __float2bfloat16_rn(v.x); lo.y = __float2bfloat16_rn(v.y);
        hi.x = __float2bfloat16_rn(v.z); hi.y = __float2bfloat16_rn(v.w);
        uint2 pk; pk.x = *(const unsigned*)&lo; pk.y = *(const unsigned*)&hi;
        *(uint2*)(Bs + n * BP + half * H + yl) = pk;
    }

    const int warp = tid >> 5, lane = tid & 31;
    const int wm = warp % NWM, wn = warp / NWM;
    const int g = lane >> 2, tg = lane & 3;
    const int m0 = wm * (MT * 16);
    const int nb0 = wn * (NT * 8);
    const int lrow = lane & 15;
    const int lcol = (lane >> 4) * 8;

    const unsigned As_u = (unsigned)__cvta_generic_to_shared(As);
    const unsigned Bs_u = (unsigned)__cvta_generic_to_shared(Bs);

    // hoisted ldmatrix lane addresses
    unsigned a_off[MT];
    #pragma unroll
    for (int mt = 0; mt < MT; mt++)
        a_off[mt] = (unsigned)(((m0 + mt * 16 + lrow) * AP + lcol) * 2);

    // B: x4 pairs -> matrices {ntile 2p: k0-7, k8-15, ntile 2p+1: k0-7, k8-15}
    const int bmm = lane >> 3, brr = lane & 7;
    unsigned b_base[NP > 0 ? NP : 1];
    #pragma unroll
    for (int p = 0; p < (NP > 0 ? NP : 1); p++) {
        int rowo = (bmm & 2) ? 8 : 0;
        int ko = (bmm & 1) * 8;
        b_base[p] = Bs_u + (unsigned)(((nb0 + p * 16 + rowo + brr) * BP + ko) * 2);
    }
    // NT==1: x2 path, lanes 0..15 addresses (matrix0 k0-7, matrix1 k8-15)
    unsigned b_base1 = Bs_u + (unsigned)(((nb0 + brr) * BP + (bmm & 1) * 8) * 2);

    float acc[MT][NT][4];
    #pragma unroll
    for (int mt = 0; mt < MT; mt++)
        #pragma unroll
        for (int nt = 0; nt < NT; nt++)
            #pragma unroll
            for (int q = 0; q < 4; q++) acc[mt][nt][q] = 0.f;

    for (int s = 0; s < NSUB; s++) {
        cp_wait<1>();
        __syncthreads();
        if (s + 2 < NSUB) {
            const char* src = (const char*)Abase + (s + 2) * KSUB * 2;
            char* dst = (char*)(As + ((s + 2) % 3) * 128 * AP);
            #pragma unroll
            for (int t = 0; t < 4; t++) {
                int r = row8 + t * 32;
                cp16(dst + r * (AP * 2) + ch8 * 16, src + (size_t)r * (X384 * 2) + ch8 * 16);
            }
        }
        cp_commit();

        const unsigned stg = As_u + (s % 3) * (128 * AP * 2);
        const unsigned soff = (unsigned)(s * KSUB * 2);

        #pragma unroll
        for (int ks = 0; ks < 4; ks++) {
            const unsigned ko = ks * 32;
            unsigned a[MT][4];
            #pragma unroll
            for (int mt = 0; mt < MT; mt++)
                ldmx4(a[mt], stg + a_off[mt] + ko);
            if constexpr (NP > 0) {
                #pragma unroll
                for (int p = 0; p < NP; p++) {
                    unsigned bb[4];
                    ldmx4(bb, b_base[p] + soff + ko);
                    #pragma unroll
                    for (int mt = 0; mt < MT; mt++) {
                        mma16816(acc[mt][2 * p],     a[mt], bb[0], bb[1]);
                        mma16816(acc[mt][2 * p + 1], a[mt], bb[2], bb[3]);
                    }
                }
            } else {
                unsigned bb[2];
                ldmx2(bb, b_base1 + soff + ko);
                #pragma unroll
                for (int mt = 0; mt < MT; mt++)
                    mma16816(acc[mt][0], a[mt], bb[0], bb[1]);
            }
        }
    }

    if (!isW) {
        const int xb = mblk % 3, hh = mblk / 3;
        #pragma unroll
        for (int nt = 0; nt < NT; nt++) {
            int nl = nb0 + nt * 8 + 2 * tg;            // local n (Bs row)
            float p0 = 0.f, p1 = 0.f;
            #pragma unroll
            for (int mt = 0; mt < MT; mt++) {
                int xf = xb * 128 + m0 + mt * 16 + g;  // global x for c[n,x]
                float c0 = __bfloat162float(Bs[nl * BP + xf]);
                float c1 = __bfloat162float(Bs[nl * BP + xf + 8]);
                float d0 = __bfloat162float(Bs[(nl + 1) * BP + xf]);
                float d1 = __bfloat162float(Bs[(nl + 1) * BP + xf + 8]);
                p0 += c0 * acc[mt][nt][0] + c1 * acc[mt][nt][2];
                p1 += d0 * acc[mt][nt][1] + d1 * acc[mt][nt][3];
            }
            #pragma unroll
            for (int sh = 4; sh < 32; sh <<= 1) {      // reduce over g
                p0 += __shfl_xor_sync(0xffffffffu, p0, sh);
                p1 += __shfl_xor_sync(0xffffffffu, p1, sh);
            }
            if (g == 0) {
                ysm[wm * NTILE + nl] = p0;
                ysm[wm * NTILE + nl + 1] = p1;
            }
        }
        __syncthreads();
        for (int n = tid; n < NTILE; n += 256) {
            float v = 0.f;
            #pragma unroll
            for (int w = 0; w < NWM; w++) v += ysm[w * NTILE + n];
            g_part[xb][hh][n0 + n] = v;
        }
    } else {
        const int hb = (mblk - 576) * 128;
        #pragma unroll
        for (int mt = 0; mt < MT; mt++) {
            int hh = hb + m0 + mt * 16 + g;
            #pragma unroll
            for (int nt = 0; nt < NT; nt++) {
                int n = n0 + nb0 + nt * 8 + 2 * tg;
                if (hh < H) {
                    g_part[3][hh][n]     = acc[mt][nt][0];
                    g_part[3][hh][n + 1] = acc[mt][nt][1];
                }
                if (hh + 8 < H) {
                    g_part[3][hh + 8][n]     = acc[mt][nt][2];
                    g_part[3][hh + 8][n + 1] = acc[mt][nt][3];
                }
            }
        }
    }
}

// ---------------------------------------------------------------------------
// Finalize: sum partials + bias, tanh, scatter to node storage
// ---------------------------------------------------------------------------
__global__ void finalize_kernel(int outBase, const float* __restrict__ bias) {
    int n = blockIdx.x, h = threadIdx.x;
    float v = g_part[0][h][n] + g_part[1][h][n] + g_part[2][h][n]
            + g_part[3][h][n] + bias[h];
    g_nodes[(size_t)(outBase + n) * H + h] = tanhf(v);
}

// ---------------------------------------------------------------------------
// Logits + log_softmax, one warp per node
// ---------------------------------------------------------------------------
__global__ void logits_kernel(const float* __restrict__ Wout_w,
                              const float* __restrict__ Wout_b,
                              float* __restrict__ out) {
    int node = (blockIdx.x * blockDim.x + threadIdx.x) >> 5;   // 63 * 8 = 504
    int lane = threadIdx.x & 31;
    const float* v = g_nodes + (size_t)node * H;
    float l[5];
    #pragma unroll
    for (int o = 0; o < 5; o++) {
        float p = 0.f;
        #pragma unroll
        for (int i = 0; i < 6; i++) {
            int idx = lane + 32 * i;
            p += v[idx] * Wout_w[o * H + idx];
        }
        #pragma unroll
        for (int s = 16; s; s >>= 1) p += __shfl_xor_sync(0xffffffffu, p, s);
        l[o] = p + Wout_b[o];
    }
    if (lane == 0) {
        float m = l[0];
        #pragma unroll
        for (int o = 1; o < 5; o++) m = fmaxf(m, l[o]);
        float s = 0.f;
        #pragma unroll
        for (int o = 0; o < 5; o++) s += expf(l[o] - m);
        float ls = logf(s);
        #pragma unroll
        for (int o = 0; o < 5; o++) out[node * 5 + o] = l[o] - m - ls;
    }
}

// ---------------------------------------------------------------------------
static inline size_t smem_bytes(int NTILE) {
    int NWM = (NTILE > 8) ? 4 : 8;
    return (size_t)3 * 128 * AP * 2 + (size_t)NTILE * BP * 2 + (size_t)NWM * NTILE * 4;
}

extern "C" void kernel_launch(void* const* d_in, const int* in_sizes, int n_in,
                              void* d_out, int out_size) {
    const float* embed  = (const float*)d_in[0];
    const float* Vt     = (const float*)d_in[1];
    const float* W      = (const float*)d_in[2];
    const float* b      = (const float*)d_in[3];
    const float* Wout_w = (const float*)d_in[4];
    const float* Wout_b = (const float*)d_in[5];
    const int*   leaf   = (const int*)d_in[6];
    float* out = (float*)d_out;

    static bool attr_set = false;
    if (!attr_set) {
        cudaFuncSetAttribute(gemm_level<64>, cudaFuncAttributeMaxDynamicSharedMemorySize, (int)smem_bytes(64));
        cudaFuncSetAttribute(gemm_level<32>, cudaFuncAttributeMaxDynamicSharedMemorySize, (int)smem_bytes(32));
        cudaFuncSetAttribute(gemm_level<16>, cudaFuncAttributeMaxDynamicSharedMemorySize, (int)smem_bytes(16));
        cudaFuncSetAttribute(gemm_level<8>,  cudaFuncAttributeMaxDynamicSharedMemorySize, (int)smem_bytes(8));
        attr_set = true;
    }

    convert_kernel<<<1728, 256>>>(Vt);
    convertWT_kernel<<<192, 128>>>(W);
    leaf_kernel<<<256, H>>>(embed, leaf);

    // level 0: 256 leaves -> 128 nodes
    gemm_level<64><<<dim3(578, 2), 256, smem_bytes(64)>>>(0, 32, 128);
    finalize_kernel<<<128, H>>>(256, b);
    // level 1: 128 -> 64
    gemm_level<64><<<dim3(578, 1), 256, smem_bytes(64)>>>(256, 16, 64);
    finalize_kernel<<<64, H>>>(384, b);
    // level 2: 64 -> 32
    gemm_level<32><<<dim3(578, 1), 256, smem_bytes(32)>>>(384, 8, 32);
    finalize_kernel<<<32, H>>>(448, b);
    // level 3: 32 -> 16
    gemm_level<16><<<dim3(578, 1), 256, smem_bytes(16)>>>(448, 4, 16);
    finalize_kernel<<<16, H>>>(480, b);
    // level 4: 16 -> 8
    gemm_level<8><<<dim3(578, 1), 256, smem_bytes(8)>>>(480, 2, 8);
    finalize_kernel<<<8, H>>>(496, b);

    logits_kernel<<<63, 256>>>(Wout_w, Wout_b, out);
}

// round 8
// speedup vs baseline: 2.6366x; 1.0066x over previous
#include <cuda_runtime.h>
#include <cuda_bf16.h>
#include <cstdint>

#define H 192
#define X384 384
#define NNODES 504   // 256 leaves + 128 + 64 + 32 + 16 + 8

#define AP 72        // A stage row stride (bf16 elems): 64 + 8 pad
#define BP 392       // B row stride (bf16 elems): 384 + 8 pad
#define KSUB 64      // k sub-chunk
#define NSUB 6       // 384 / 64

// Scratch (allocation-free rule: __device__ globals)
__device__ __nv_bfloat16 g_Vbf[(size_t)H * X384 * X384];  // 54 MB bf16 V
__device__ __nv_bfloat16 g_WTbf[256 * X384];              // W^T bf16, rows 192..255 stay zero
__device__ float g_nodes[NNODES * H];
__device__ float g_part[4][H][128];                        // 3 x-block partials + Wx

// ---------------------------------------------------------------------------
// async-copy / ldmatrix helpers
// ---------------------------------------------------------------------------
__device__ __forceinline__ void cp16(void* smem, const void* gmem) {
    unsigned s = (unsigned)__cvta_generic_to_shared(smem);
    asm volatile("cp.async.cg.shared.global [%0], [%1], 16;\n" :: "r"(s), "l"(gmem));
}
__device__ __forceinline__ void cp_commit() { asm volatile("cp.async.commit_group;\n"); }
template <int N>
__device__ __forceinline__ void cp_wait() { asm volatile("cp.async.wait_group %0;\n" :: "n"(N)); }

__device__ __forceinline__ void ldmx4(unsigned* a, unsigned saddr) {
    asm volatile("ldmatrix.sync.aligned.m8n8.x4.shared.b16 {%0,%1,%2,%3}, [%4];"
                 : "=r"(a[0]), "=r"(a[1]), "=r"(a[2]), "=r"(a[3]) : "r"(saddr));
}
__device__ __forceinline__ void ldmx2(unsigned* a, unsigned saddr) {
    asm volatile("ldmatrix.sync.aligned.m8n8.x2.shared.b16 {%0,%1}, [%2];"
                 : "=r"(a[0]), "=r"(a[1]) : "r"(saddr));
}
__device__ __forceinline__ void mma16816(float* d, const unsigned* a, unsigned b0, unsigned b1) {
    asm volatile(
        "mma.sync.aligned.m16n8k16.row.col.f32.bf16.bf16.f32 "
        "{%0,%1,%2,%3},{%4,%5,%6,%7},{%8,%9},{%0,%1,%2,%3};"
        : "+f"(d[0]), "+f"(d[1]), "+f"(d[2]), "+f"(d[3])
        : "r"(a[0]), "r"(a[1]), "r"(a[2]), "r"(a[3]), "r"(b0), "r"(b1));
}

// ---------------------------------------------------------------------------
// Kernel 1: convert Vt fp32 -> bf16
// ---------------------------------------------------------------------------
__global__ void convert_kernel(const float* __restrict__ Vt) {
    size_t t = (size_t)blockIdx.x * 256 + threadIdx.x;
    const float4* src = (const float4*)Vt;
    const size_t stride = 1728ull * 256ull;
    #pragma unroll 16
    for (int j = 0; j < 16; j++) {
        size_t i = t + stride * j;
        float4 v = src[i];
        __nv_bfloat162 lo, hi;
        lo.x = __float2bfloat16_rn(v.x); lo.y = __float2bfloat16_rn(v.y);
        hi.x = __float2bfloat16_rn(v.z); hi.y = __float2bfloat16_rn(v.w);
        uint2 pk; pk.x = *(const unsigned*)&lo; pk.y = *(const unsigned*)&hi;
        *(uint2*)(g_Vbf + 4 * i) = pk;
    }
}

// W^T bf16: g_WTbf[h][y] = W[y][h]
__global__ void convertWT_kernel(const float* __restrict__ W) {
    int h = blockIdx.x;
    for (int y = threadIdx.x; y < X384; y += blockDim.x)
        g_WTbf[h * X384 + y] = __float2bfloat16_rn(W[y * H + h]);
}

// ---------------------------------------------------------------------------
// Kernel 2: leaf embedding gather
// ---------------------------------------------------------------------------
__global__ void leaf_kernel(const float* __restrict__ embed, const int* __restrict__ leaf_ids) {
    int n = blockIdx.x, t = threadIdx.x;
    g_nodes[n * H + t] = embed[(size_t)leaf_ids[n] * H + t];
}

// ---------------------------------------------------------------------------
// Main GEMM per level. ldmatrix-fed, fragment double-buffered mainloop.
// grid = (578, Nlev/NTILE), 256 threads.
// ---------------------------------------------------------------------------
template <int NTILE>
__global__ void __launch_bounds__(256)
gemm_level(int prevBase, int prevN, int Nlev) {
    constexpr int NWN = (NTILE > 8) ? 2 : 1;     // n-warp columns
    constexpr int NWM = 8 / NWN;                 // m-warp rows
    constexpr int MT  = 128 / (NWM * 16);        // m16 tiles per warp (2 or 1)
    constexpr int NT  = (NTILE / NWN) / 8;       // n8 tiles per warp
    constexpr int NP  = NT / 2;                  // ldmatrix.x4 pairs (0 when NT==1)
    constexpr int NBR = (NP > 0) ? NP * 4 : 2;   // b fragment regs per k-step

    extern __shared__ char smraw[];
    __nv_bfloat16* As = (__nv_bfloat16*)smraw;         // [3][128][AP]
    __nv_bfloat16* Bs = As + 3 * 128 * AP;             // [NTILE][BP]
    float* ysm = (float*)(Bs + NTILE * BP);            // [NWM][NTILE]

    const int mblk = blockIdx.x;
    const int n0 = blockIdx.y * NTILE;
    const bool isW = (mblk >= 576);
    const __nv_bfloat16* __restrict__ Abase = isW
        ? (g_WTbf + (size_t)(mblk - 576) * 128 * X384)
        : (g_Vbf + ((size_t)(mblk / 3) * X384 + (mblk % 3) * 128) * X384);

    const int tid = threadIdx.x;
    const int row8 = tid >> 3, ch8 = tid & 7;          // 256 thr x 4 chunks = 1024 chunks/stage

    // prologue: stages 0,1
    #pragma unroll
    for (int s = 0; s < 2; s++) {
        const char* src = (const char*)Abase + s * KSUB * 2;
        char* dst = (char*)(As + s * 128 * AP);
        #pragma unroll
        for (int t = 0; t < 4; t++) {
            int r = row8 + t * 32;
            cp16(dst + r * (AP * 2) + ch8 * 16, src + (size_t)r * (X384 * 2) + ch8 * 16);
        }
        cp_commit();
    }

    // B gather: Bs[n][y] = c[n0+n, y] = concat(childL, childR), fp32 -> bf16
    const int npt = Nlev >> 3;
    for (int i = tid; i < NTILE * 96; i += 256) {
        int n = i / 96, q = i - n * 96;
        int half = q / 48, yl = (q - half * 48) * 4;
        int ng = n0 + n;
        int bt = ng / npt, j = ng - bt * npt;
        int child = prevBase + bt * prevN + 2 * j + half;
        float4 v = *(const float4*)(g_nodes + (size_t)child * H + yl);
        __nv_bfloat162 lo, hi;
        lo.x = __float2bfloat16_rn(v.x); lo.y = __float2bfloat16_rn(v.y);
        hi.x = __float2bfloat16_rn(v.z); hi.y = __float2bfloat16_rn(v.w);
        uint2 pk; pk.x = *(const unsigned*)&lo; pk.y = *(const unsigned*)&hi;
        *(uint2*)(Bs + n * BP + half * H + yl) = pk;
    }

    const int warp = tid >> 5, lane = tid & 31;
    const int wm = warp % NWM, wn = warp / NWM;
    const int g = lane >> 2, tg = lane & 3;
    const int m0 = wm * (MT * 16);
    const int nb0 = wn * (NT * 8);
    const int lrow = lane & 15;
    const int lcol = (lane >> 4) * 8;

    const unsigned As_u = (unsigned)__cvta_generic_to_shared(As);
    const unsigned Bs_u = (unsigned)__cvta_generic_to_shared(Bs);

    // hoisted ldmatrix lane addresses
    unsigned a_off[MT];
    #pragma unroll
    for (int mt = 0; mt < MT; mt++)
        a_off[mt] = (unsigned)(((m0 + mt * 16 + lrow) * AP + lcol) * 2);

    // B: x4 pairs -> matrices {ntile 2p: k0-7, k8-15, ntile 2p+1: k0-7, k8-15}
    const int bmm = lane >> 3, brr = lane & 7;
    unsigned b_base[NP > 0 ? NP : 1];
    #pragma unroll
    for (int p = 0; p < (NP > 0 ? NP : 1); p++) {
        int rowo = (bmm & 2) ? 8 : 0;
        int ko = (bmm & 1) * 8;
        b_base[p] = Bs_u + (unsigned)(((nb0 + p * 16 + rowo + brr) * BP + ko) * 2);
    }
    unsigned b_base1 = Bs_u + (unsigned)(((nb0 + brr) * BP + (bmm & 1) * 8) * 2);

    float acc[MT][NT][4];
    #pragma unroll
    for (int mt = 0; mt < MT; mt++)
        #pragma unroll
        for (int nt = 0; nt < NT; nt++)
            #pragma unroll
            for (int q = 0; q < 4; q++) acc[mt][nt][q] = 0.f;

    // fragment double buffers
    unsigned afr[2][MT][4];
    unsigned bfr[2][NBR];

    for (int s = 0; s < NSUB; s++) {
        cp_wait<1>();
        __syncthreads();
        if (s + 2 < NSUB) {
            const char* src = (const char*)Abase + (s + 2) * KSUB * 2;
            char* dst = (char*)(As + ((s + 2) % 3) * 128 * AP);
            #pragma unroll
            for (int t = 0; t < 4; t++) {
                int r = row8 + t * 32;
                cp16(dst + r * (AP * 2) + ch8 * 16, src + (size_t)r * (X384 * 2) + ch8 * 16);
            }
        }
        cp_commit();

        const unsigned a_stg = As_u + (s % 3) * (128 * AP * 2);
        const unsigned soff = (unsigned)(s * KSUB * 2);

        // prefetch k-step 0 fragments
        #pragma unroll
        for (int mt = 0; mt < MT; mt++) ldmx4(afr[0][mt], a_stg + a_off[mt]);
        if constexpr (NP > 0) {
            #pragma unroll
            for (int p = 0; p < NP; p++) ldmx4(&bfr[0][4 * p], b_base[p] + soff);
        } else {
            ldmx2(bfr[0], b_base1 + soff);
        }

        #pragma unroll
        for (int ks = 0; ks < 4; ks++) {
            const int cur = ks & 1, nxt = cur ^ 1;
            if (ks < 3) {                              // prefetch next k-step
                const unsigned ko = (ks + 1) * 32;
                #pragma unroll
                for (int mt = 0; mt < MT; mt++) ldmx4(afr[nxt][mt], a_stg + a_off[mt] + ko);
                if constexpr (NP > 0) {
                    #pragma unroll
                    for (int p = 0; p < NP; p++) ldmx4(&bfr[nxt][4 * p], b_base[p] + soff + ko);
                } else {
                    ldmx2(bfr[nxt], b_base1 + soff + ko);
                }
            }
            if constexpr (NP > 0) {
                #pragma unroll
                for (int p = 0; p < NP; p++)
                    #pragma unroll
                    for (int mt = 0; mt < MT; mt++) {
                        mma16816(acc[mt][2 * p],     afr[cur][mt], bfr[cur][4 * p],     bfr[cur][4 * p + 1]);
                        mma16816(acc[mt][2 * p + 1], afr[cur][mt], bfr[cur][4 * p + 2], bfr[cur][4 * p + 3]);
                    }
            } else {
                #pragma unroll
                for (int mt = 0; mt < MT; mt++)
                    mma16816(acc[mt][0], afr[cur][mt], bfr[cur][0], bfr[cur][1]);
            }
        }
    }

    if (!isW) {
        const int xb = mblk % 3, hh = mblk / 3;
        #pragma unroll
        for (int nt = 0; nt < NT; nt++) {
            int nl = nb0 + nt * 8 + 2 * tg;            // local n (Bs row)
            float p0 = 0.f, p1 = 0.f;
            #pragma unroll
            for (int mt = 0; mt < MT; mt++) {
                int xf = xb * 128 + m0 + mt * 16 + g;  // global x for c[n,x]
                float c0 = __bfloat162float(Bs[nl * BP + xf]);
                float c1 = __bfloat162float(Bs[nl * BP + xf + 8]);
                float d0 = __bfloat162float(Bs[(nl + 1) * BP + xf]);
                float d1 = __bfloat162float(Bs[(nl + 1) * BP + xf + 8]);
                p0 += c0 * acc[mt][nt][0] + c1 * acc[mt][nt][2];
                p1 += d0 * acc[mt][nt][1] + d1 * acc[mt][nt][3];
            }
            #pragma unroll
            for (int sh = 4; sh < 32; sh <<= 1) {      // reduce over g
                p0 += __shfl_xor_sync(0xffffffffu, p0, sh);
                p1 += __shfl_xor_sync(0xffffffffu, p1, sh);
            }
            if (g == 0) {
                ysm[wm * NTILE + nl] = p0;
                ysm[wm * NTILE + nl + 1] = p1;
            }
        }
        __syncthreads();
        for (int n = tid; n < NTILE; n += 256) {
            float v = 0.f;
            #pragma unroll
            for (int w = 0; w < NWM; w++) v += ysm[w * NTILE + n];
            g_part[xb][hh][n0 + n] = v;
        }
    } else {
        const int hb = (mblk - 576) * 128;
        #pragma unroll
        for (int mt = 0; mt < MT; mt++) {
            int hh = hb + m0 + mt * 16 + g;
            #pragma unroll
            for (int nt = 0; nt < NT; nt++) {
                int n = n0 + nb0 + nt * 8 + 2 * tg;
                if (hh < H) {
                    g_part[3][hh][n]     = acc[mt][nt][0];
                    g_part[3][hh][n + 1] = acc[mt][nt][1];
                }
                if (hh + 8 < H) {
                    g_part[3][hh + 8][n]     = acc[mt][nt][2];
                    g_part[3][hh + 8][n + 1] = acc[mt][nt][3];
                }
            }
        }
    }
}

// ---------------------------------------------------------------------------
// Finalize: sum partials + bias, tanh, scatter to node storage
// ---------------------------------------------------------------------------
__global__ void finalize_kernel(int outBase, const float* __restrict__ bias) {
    int n = blockIdx.x, h = threadIdx.x;
    float v = g_part[0][h][n] + g_part[1][h][n] + g_part[2][h][n]
            + g_part[3][h][n] + bias[h];
    g_nodes[(size_t)(outBase + n) * H + h] = tanhf(v);
}

// ---------------------------------------------------------------------------
// Logits + log_softmax, one warp per node
// ---------------------------------------------------------------------------
__global__ void logits_kernel(const float* __restrict__ Wout_w,
                              const float* __restrict__ Wout_b,
                              float* __restrict__ out) {
    int node = (blockIdx.x * blockDim.x + threadIdx.x) >> 5;   // 63 * 8 = 504
    int lane = threadIdx.x & 31;
    const float* v = g_nodes + (size_t)node * H;
    float l[5];
    #pragma unroll
    for (int o = 0; o < 5; o++) {
        float p = 0.f;
        #pragma unroll
        for (int i = 0; i < 6; i++) {
            int idx = lane + 32 * i;
            p += v[idx] * Wout_w[o * H + idx];
        }
        #pragma unroll
        for (int s = 16; s; s >>= 1) p += __shfl_xor_sync(0xffffffffu, p, s);
        l[o] = p + Wout_b[o];
    }
    if (lane == 0) {
        float m = l[0];
        #pragma unroll
        for (int o = 1; o < 5; o++) m = fmaxf(m, l[o]);
        float s = 0.f;
        #pragma unroll
        for (int o = 0; o < 5; o++) s += expf(l[o] - m);
        float ls = logf(s);
        #pragma unroll
        for (int o = 0; o < 5; o++) out[node * 5 + o] = l[o] - m - ls;
    }
}

// ---------------------------------------------------------------------------
static inline size_t smem_bytes(int NTILE) {
    int NWM = (NTILE > 8) ? 4 : 8;
    return (size_t)3 * 128 * AP * 2 + (size_t)NTILE * BP * 2 + (size_t)NWM * NTILE * 4;
}

extern "C" void kernel_launch(void* const* d_in, const int* in_sizes, int n_in,
                              void* d_out, int out_size) {
    const float* embed  = (const float*)d_in[0];
    const float* Vt     = (const float*)d_in[1];
    const float* W      = (const float*)d_in[2];
    const float* b      = (const float*)d_in[3];
    const float* Wout_w = (const float*)d_in[4];
    const float* Wout_b = (const float*)d_in[5];
    const int*   leaf   = (const int*)d_in[6];
    float* out = (float*)d_out;

    static bool attr_set = false;
    if (!attr_set) {
        cudaFuncSetAttribute(gemm_level<64>, cudaFuncAttributeMaxDynamicSharedMemorySize, (int)smem_bytes(64));
        cudaFuncSetAttribute(gemm_level<32>, cudaFuncAttributeMaxDynamicSharedMemorySize, (int)smem_bytes(32));
        cudaFuncSetAttribute(gemm_level<16>, cudaFuncAttributeMaxDynamicSharedMemorySize, (int)smem_bytes(16));
        cudaFuncSetAttribute(gemm_level<8>,  cudaFuncAttributeMaxDynamicSharedMemorySize, (int)smem_bytes(8));
        attr_set = true;
    }

    convert_kernel<<<1728, 256>>>(Vt);
    convertWT_kernel<<<192, 128>>>(W);
    leaf_kernel<<<256, H>>>(embed, leaf);

    // level 0: 256 leaves -> 128 nodes
    gemm_level<64><<<dim3(578, 2), 256, smem_bytes(64)>>>(0, 32, 128);
    finalize_kernel<<<128, H>>>(256, b);
    // level 1: 128 -> 64
    gemm_level<64><<<dim3(578, 1), 256, smem_bytes(64)>>>(256, 16, 64);
    finalize_kernel<<<64, H>>>(384, b);
    // level 2: 64 -> 32
    gemm_level<32><<<dim3(578, 1), 256, smem_bytes(32)>>>(384, 8, 32);
    finalize_kernel<<<32, H>>>(448, b);
    // level 3: 32 -> 16
    gemm_level<16><<<dim3(578, 1), 256, smem_bytes(16)>>>(448, 4, 16);
    finalize_kernel<<<16, H>>>(480, b);
    // level 4: 16 -> 8
    gemm_level<8><<<dim3(578, 1), 256, smem_bytes(8)>>>(480, 2, 8);
    finalize_kernel<<<8, H>>>(496, b);

    logits_kernel<<<63, 256>>>(Wout_w, Wout_b, out);
}

// round 11
// speedup vs baseline: 2.8716x; 1.0891x over previous
#include <cuda_runtime.h>
#include <cuda_bf16.h>
#include <cstdint>

#define H 192
#define X384 384
#define NNODES 504   // 256 leaves + 128 + 64 + 32 + 16 + 8
#define NSUB 6       // k stages of 64

// Scratch (allocation-free rule: __device__ globals)
__device__ __nv_bfloat16 g_Vbf[(size_t)H * X384 * X384];  // 54 MB bf16 V
__device__ __nv_bfloat16 g_WTbf[256 * X384];              // W^T bf16, rows 192..255 zero
__device__ __nv_bfloat16 g_cB[128 * X384];                // current-level node vectors, bf16
__device__ float g_nodes[NNODES * H];
__device__ float g_part[7][H][128];                        // 6 x-block partials + Wx

// ---------------------------------------------------------------------------
// helpers
// ---------------------------------------------------------------------------
__device__ __forceinline__ void cp16(void* smem, const void* gmem) {
    unsigned s = (unsigned)__cvta_generic_to_shared(smem);
    asm volatile("cp.async.cg.shared.global [%0], [%1], 16;\n" :: "r"(s), "l"(gmem));
}
__device__ __forceinline__ void cp_commit() { asm volatile("cp.async.commit_group;\n"); }
template <int N>
__device__ __forceinline__ void cp_wait() { asm volatile("cp.async.wait_group %0;\n" :: "n"(N)); }

__device__ __forceinline__ void ldmx4(unsigned* a, unsigned saddr) {
    asm volatile("ldmatrix.sync.aligned.m8n8.x4.shared.b16 {%0,%1,%2,%3}, [%4];"
                 : "=r"(a[0]), "=r"(a[1]), "=r"(a[2]), "=r"(a[3]) : "r"(saddr));
}
__device__ __forceinline__ void ldmx2(unsigned* a, unsigned saddr) {
    asm volatile("ldmatrix.sync.aligned.m8n8.x2.shared.b16 {%0,%1}, [%2];"
                 : "=r"(a[0]), "=r"(a[1]) : "r"(saddr));
}
__device__ __forceinline__ void mma16816(float* d, const unsigned* a, unsigned b0, unsigned b1) {
    asm volatile(
        "mma.sync.aligned.m16n8k16.row.col.f32.bf16.bf16.f32 "
        "{%0,%1,%2,%3},{%4,%5,%6,%7},{%8,%9},{%0,%1,%2,%3};"
        : "+f"(d[0]), "+f"(d[1]), "+f"(d[2]), "+f"(d[3])
        : "r"(a[0]), "r"(a[1]), "r"(a[2]), "r"(a[3]), "r"(b0), "r"(b1));
}

// ---------------------------------------------------------------------------
// Kernel 1: convert Vt fp32 -> bf16
// ---------------------------------------------------------------------------
__global__ void convert_kernel(const float* __restrict__ Vt) {
    size_t t = (size_t)blockIdx.x * 256 + threadIdx.x;
    const float4* src = (const float4*)Vt;
    const size_t stride = 1728ull * 256ull;
    #pragma unroll 16
    for (int j = 0; j < 16; j++) {
        size_t i = t + stride * j;
        float4 v = src[i];
        __nv_bfloat162 lo, hi;
        lo.x = __float2bfloat16_rn(v.x); lo.y = __float2bfloat16_rn(v.y);
        hi.x = __float2bfloat16_rn(v.z); hi.y = __float2bfloat16_rn(v.w);
        uint2 pk; pk.x = *(const unsigned*)&lo; pk.y = *(const unsigned*)&hi;
        *(uint2*)(g_Vbf + 4 * i) = pk;
    }
}

// W^T bf16: g_WTbf[h][y] = W[y][h]; rows >= 192 zero
__global__ void convertWT_kernel(const float* __restrict__ W) {
    int h = blockIdx.x;
    for (int y = threadIdx.x; y < X384; y += blockDim.x)
        g_WTbf[h * X384 + y] = __float2bfloat16_rn(h < H ? W[y * H + h] : 0.f);
}

// ---------------------------------------------------------------------------
// Kernel 2: leaf embedding gather
// ---------------------------------------------------------------------------
__global__ void leaf_kernel(const float* __restrict__ embed, const int* __restrict__ leaf_ids) {
    int n = blockIdx.x, t = threadIdx.x;
    g_nodes[n * H + t] = embed[(size_t)leaf_ids[n] * H + t];
}

// ---------------------------------------------------------------------------
// Per-level prep: build bf16 B matrix g_cB[n][y] = concat(childL, childR).
// grid = padded node count (>= Nlev), 192 threads. Rows >= Nlev zeroed.
// ---------------------------------------------------------------------------
__global__ void prep_kernel(int prevBase, int prevN, int Nlev) {
    int n = blockIdx.x, t = threadIdx.x;
    __nv_bfloat16 l = __float2bfloat16_rn(0.f), r = l;
    if (n < Nlev) {
        int npt = Nlev >> 3;
        int bt = n / npt, j = n - bt * npt;
        int child = prevBase + bt * prevN + 2 * j;
        l = __float2bfloat16_rn(g_nodes[(size_t)child * H + t]);
        r = __float2bfloat16_rn(g_nodes[(size_t)(child + 1) * H + t]);
    }
    g_cB[n * X384 + t] = l;
    g_cB[n * X384 + H + t] = r;
}

// ---------------------------------------------------------------------------
// Level GEMM, M=64 row blocks, XOR-swizzled smem (no padding), 3 CTAs/SM.
//   mblk < 1152 : A = V rows (h = mblk/6, x-block = mblk%6) -> U[x,n],
//                 epilogue y[n] += sum_x c[n,x] U[x,n] -> g_part[xb][h][n]
//   mblk >=1152 : A = W^T rows (64 per block) -> g_part[6][h][n]
// A smem stage: 64 rows x 64 cols bf16 (128B rows, chunk XOR swizzle).
// B smem: NTILE rows x 384 cols bf16 (768B rows, chunk XOR swizzle),
//         loaded via cp.async in the SAME commit group as matching A stage.
// grid = (1156, ceil(Nlev/NTILE)), 256 threads (4 m-warps x 2 n-warps).
// ---------------------------------------------------------------------------
template <int NTILE>
__global__ void __launch_bounds__(256)
gemm_level() {
    constexpr int NT = NTILE / 16;               // n8 tiles per n-warp (4, 2, 1)
    constexpr int NP = NT / 2;                   // ldmatrix.x4 pairs (0 when NT==1)
    constexpr int NBCH = NTILE * 8;              // B chunks per stage

    extern __shared__ char smraw[];
    char* As = smraw;                            // [3][64][128B]
    char* Bp = smraw + 3 * 8192;                 // [NTILE][768B]
    float* ysm = (float*)(Bp + NTILE * 768);     // [4][NTILE]

    const int mblk = blockIdx.x;
    const int n0 = blockIdx.y * NTILE;
    const bool isW = (mblk >= 1152);
    const __nv_bfloat16* __restrict__ Ag = isW
        ? (g_WTbf + (size_t)(mblk - 1152) * 64 * X384)
        : (g_Vbf + ((size_t)(mblk / 6) * X384 + (mblk % 6) * 64) * X384);

    const int tid = threadIdx.x;
    const int ar = tid >> 3, ac = tid & 7;       // A: rows {ar, ar+32}, chunk ac

    // ---- prologue: stages 0,1 (A + B k-slice in one group each) ----
    #pragma unroll
    for (int s = 0; s < 2; s++) {
        char* Ad = As + s * 8192;
        #pragma unroll
        for (int t = 0; t < 2; t++) {
            int r = ar + t * 32;
            cp16(Ad + r * 128 + (((ac ^ (r & 7)) << 4)), Ag + r * X384 + s * 64 + ac * 8);
        }
        for (int j = tid; j < NBCH; j += 256) {
            int n = j >> 3, c = j & 7;
            cp16(Bp + n * 768 + ((((s * 8 + c) ^ (n & 7)) << 4)),
                 g_cB + (size_t)(n0 + n) * X384 + s * 64 + c * 8);
        }
        cp_commit();
    }

    const int warp = tid >> 5, lane = tid & 31;
    const int wm = warp & 3, wn = warp >> 2;     // 4 m-warps x 2 n-warps
    const int g = lane >> 2, tg = lane & 3;
    const int m0 = wm * 16;
    const int nb0 = wn * (NT * 8);

    const unsigned As_u = (unsigned)__cvta_generic_to_shared(As);
    const unsigned Bs_u = (unsigned)__cvta_generic_to_shared(Bp);

    // A ldmatrix addresses (stage-relative, one per k-step)
    const int am = m0 + (lane & 15);
    unsigned a_off[4];
    #pragma unroll
    for (int ks = 0; ks < 4; ks++) {
        int c = ks * 2 + (lane >> 4);
        a_off[ks] = (unsigned)(am * 128 + ((c ^ (am & 7)) << 4));
    }

    // B ldmatrix lane geometry
    const int bmm = lane >> 3, brr = lane & 7;
    const int rowo = (bmm & 2) ? 8 : 0, kos = bmm & 1;
    unsigned b_row[NP > 0 ? NP : 1];
    unsigned b_xm[NP > 0 ? NP : 1];
    #pragma unroll
    for (int p = 0; p < (NP > 0 ? NP : 1); p++) {
        int nr = nb0 + p * 16 + rowo + brr;
        b_row[p] = (unsigned)(nr * 768);
        b_xm[p] = (unsigned)(nr & 7);
    }
    const int nr1 = nb0 + brr;                   // NT==1 (x2) path
    const unsigned b_row1 = (unsigned)(nr1 * 768), b_xm1 = (unsigned)(nr1 & 7);

    float acc[NT][4];
    #pragma unroll
    for (int nt = 0; nt < NT; nt++)
        #pragma unroll
        for (int q = 0; q < 4; q++) acc[nt][q] = 0.f;

    // ---- mainloop over 6 k-stages ----
    for (int s = 0; s < NSUB; s++) {
        if (s == NSUB - 1) cp_wait<0>(); else cp_wait<1>();
        __syncthreads();
        int sn = s + 2;
        if (sn < NSUB) {                          // refill buffer freed by stage s-1
            char* Ad = As + (sn % 3) * 8192;
            #pragma unroll
            for (int t = 0; t < 2; t++) {
                int r = ar + t * 32;
                cp16(Ad + r * 128 + (((ac ^ (r & 7)) << 4)), Ag + r * X384 + sn * 64 + ac * 8);
            }
            for (int j = tid; j < NBCH; j += 256) {
                int n = j >> 3, c = j & 7;
                cp16(Bp + n * 768 + ((((sn * 8 + c) ^ (n & 7)) << 4)),
                     g_cB + (size_t)(n0 + n) * X384 + sn * 64 + c * 8);
            }
            cp_commit();
        }

        const unsigned a_stg = As_u + (s % 3) * 8192;
        const unsigned cb = (unsigned)(s * 8 + kos);

        #pragma unroll
        for (int ks = 0; ks < 4; ks++) {
            unsigned a[4];
            ldmx4(a, a_stg + a_off[ks]);
            if constexpr (NP > 0) {
                #pragma unroll
                for (int p = 0; p < NP; p++) {
                    unsigned bb[4];
                    unsigned c = cb + ks * 2;
                    ldmx4(bb, Bs_u + b_row[p] + ((c ^ b_xm[p]) << 4));
                    mma16816(acc[2 * p],     a, bb[0], bb[1]);
                    mma16816(acc[2 * p + 1], a, bb[2], bb[3]);
                }
            } else {
                unsigned bb[2];
                unsigned c = cb + ks * 2;
                ldmx2(bb, Bs_u + b_row1 + ((c ^ b_xm1) << 4));
                mma16816(acc[0], a, bb[0], bb[1]);
            }
        }
    }

    if (!isW) {
        const int xb = mblk % 6, hh = mblk / 6;
        #pragma unroll
        for (int nt = 0; nt < NT; nt++) {
            int nl = nb0 + nt * 8 + 2 * tg;       // local n (Bs row)
            // c[n, xf] from swizzled B smem
            int xf = xb * 64 + m0 + g;            // global x for this thread's rows
            auto bld = [&](int n, int col) -> float {
                unsigned off = (unsigned)(n * 768 + (((col >> 3) ^ (n & 7)) << 4) + ((col & 7) << 1));
                return __bfloat162float(*(const __nv_bfloat16*)(Bp + off));
            };
            float p0 = bld(nl, xf)     * acc[nt][0] + bld(nl, xf + 8)     * acc[nt][2];
            float p1 = bld(nl + 1, xf) * acc[nt][1] + bld(nl + 1, xf + 8) * acc[nt][3];
            #pragma unroll
            for (int sh = 4; sh < 32; sh <<= 1) { // reduce over g
                p0 += __shfl_xor_sync(0xffffffffu, p0, sh);
                p1 += __shfl_xor_sync(0xffffffffu, p1, sh);
            }
            if (g == 0) {
                ysm[wm * NTILE + nl] = p0;
                ysm[wm * NTILE + nl + 1] = p1;
            }
        }
        __syncthreads();
        for (int n = tid; n < NTILE; n += 256) {
            float v = ysm[n] + ysm[NTILE + n] + ysm[2 * NTILE + n] + ysm[3 * NTILE + n];
            g_part[xb][hh][n0 + n] = v;
        }
    } else {
        const int hb = (mblk - 1152) * 64;
        int hh = hb + m0 + g;
        #pragma unroll
        for (int nt = 0; nt < NT; nt++) {
            int n = n0 + nb0 + nt * 8 + 2 * tg;
            if (hh < H) {
                g_part[6][hh][n]     = acc[nt][0];
                g_part[6][hh][n + 1] = acc[nt][1];
            }
            if (hh + 8 < H) {
                g_part[6][hh + 8][n]     = acc[nt][2];
                g_part[6][hh + 8][n + 1] = acc[nt][3];
            }
        }
    }
}

// ---------------------------------------------------------------------------
// Finalize: sum partials + bias, tanh, scatter to node storage
// ---------------------------------------------------------------------------
__global__ void finalize_kernel(int outBase, const float* __restrict__ bias) {
    int n = blockIdx.x, h = threadIdx.x;
    float v = bias[h];
    #pragma unroll
    for (int i = 0; i < 7; i++) v += g_part[i][h][n];
    g_nodes[(size_t)(outBase + n) * H + h] = tanhf(v);
}

// ---------------------------------------------------------------------------
// Logits + log_softmax, one warp per node
// ---------------------------------------------------------------------------
__global__ void logits_kernel(const float* __restrict__ Wout_w,
                              const float* __restrict__ Wout_b,
                              float* __restrict__ out) {
    int node = (blockIdx.x * blockDim.x + threadIdx.x) >> 5;   // 63 * 8 = 504
    int lane = threadIdx.x & 31;
    const float* v = g_nodes + (size_t)node * H;
    float l[5];
    #pragma unroll
    for (int o = 0; o < 5; o++) {
        float p = 0.f;
        #pragma unroll
        for (int i = 0; i < 6; i++) {
            int idx = lane + 32 * i;
            p += v[idx] * Wout_w[o * H + idx];
        }
        #pragma unroll
        for (int s = 16; s; s >>= 1) p += __shfl_xor_sync(0xffffffffu, p, s);
        l[o] = p + Wout_b[o];
    }
    if (lane == 0) {
        float m = l[0];
        #pragma unroll
        for (int o = 1; o < 5; o++) m = fmaxf(m, l[o]);
        float s = 0.f;
        #pragma unroll
        for (int o = 0; o < 5; o++) s += expf(l[o] - m);
        float ls = logf(s);
        #pragma unroll
        for (int o = 0; o < 5; o++) out[node * 5 + o] = l[o] - m - ls;
    }
}

// ---------------------------------------------------------------------------
static inline size_t smem_bytes(int NTILE) {
    return (size_t)3 * 8192 + (size_t)NTILE * 768 + (size_t)4 * NTILE * 4;
}

extern "C" void kernel_launch(void* const* d_in, const int* in_sizes, int n_in,
                              void* d_out, int out_size) {
    const float* embed  = (const float*)d_in[0];
    const float* Vt     = (const float*)d_in[1];
    const float* W      = (const float*)d_in[2];
    const float* b      = (const float*)d_in[3];
    const float* Wout_w = (const float*)d_in[4];
    const float* Wout_b = (const float*)d_in[5];
    const int*   leaf   = (const int*)d_in[6];
    float* out = (float*)d_out;

    static bool attr_set = false;
    if (!attr_set) {
        cudaFuncSetAttribute(gemm_level<64>, cudaFuncAttributeMaxDynamicSharedMemorySize, (int)smem_bytes(64));
        cudaFuncSetAttribute(gemm_level<32>, cudaFuncAttributeMaxDynamicSharedMemorySize, (int)smem_bytes(32));
        cudaFuncSetAttribute(gemm_level<16>, cudaFuncAttributeMaxDynamicSharedMemorySize, (int)smem_bytes(16));
        attr_set = true;
    }

    convert_kernel<<<1728, 256>>>(Vt);
    convertWT_kernel<<<256, 128>>>(W);
    leaf_kernel<<<256, H>>>(embed, leaf);

    // level 0: 256 leaves -> 128 nodes
    prep_kernel<<<128, H>>>(0, 32, 128);
    gemm_level<64><<<dim3(1156, 2), 256, smem_bytes(64)>>>();
    finalize_kernel<<<128, H>>>(256, b);
    // level 1: 128 -> 64
    prep_kernel<<<64, H>>>(256, 16, 64);
    gemm_level<64><<<dim3(1156, 1), 256, smem_bytes(64)>>>();
    finalize_kernel<<<64, H>>>(384, b);
    // level 2: 64 -> 32
    prep_kernel<<<32, H>>>(384, 8, 32);
    gemm_level<32><<<dim3(1156, 1), 256, smem_bytes(32)>>>();
    finalize_kernel<<<32, H>>>(448, b);
    // level 3: 32 -> 16
    prep_kernel<<<16, H>>>(448, 4, 16);
    gemm_level<16><<<dim3(1156, 1), 256, smem_bytes(16)>>>();
    finalize_kernel<<<16, H>>>(480, b);
    // level 4: 16 -> 8 (padded to NTILE=16)
    prep_kernel<<<16, H>>>(480, 2, 8);
    gemm_level<16><<<dim3(1156, 1), 256, smem_bytes(16)>>>();
    finalize_kernel<<<8, H>>>(496, b);

    logits_kernel<<<63, 256>>>(Wout_w, Wout_b, out);
}

// round 14
// speedup vs baseline: 3.0251x; 1.0535x over previous
#include <cuda_runtime.h>
#include <cuda_bf16.h>
#include <cstdint>

#define H 192
#define X384 384
#define NNODES 504   // 256 leaves + 128 + 64 + 32 + 16 + 8
#define NSUB 6       // k stages of 64

// Scratch (allocation-free rule: __device__ globals)
__device__ __nv_bfloat16 g_Vbf[(size_t)H * X384 * X384];  // 54 MB bf16 V
__device__ __nv_bfloat16 g_WTbf[256 * X384];              // W^T bf16, rows 192..255 zero
__device__ __nv_bfloat16 g_cB[128 * X384];                // current-level node vectors, bf16
__device__ float g_nodes[NNODES * H];
__device__ float g_part[7][H][128];                        // 6 x-block partials + Wx

// ---------------------------------------------------------------------------
// helpers
// ---------------------------------------------------------------------------
__device__ __forceinline__ void cp16(void* smem, const void* gmem) {
    unsigned s = (unsigned)__cvta_generic_to_shared(smem);
    asm volatile("cp.async.cg.shared.global [%0], [%1], 16;\n" :: "r"(s), "l"(gmem));
}
__device__ __forceinline__ void cp_commit() { asm volatile("cp.async.commit_group;\n"); }
template <int N>
__device__ __forceinline__ void cp_wait() { asm volatile("cp.async.wait_group %0;\n" :: "n"(N)); }

__device__ __forceinline__ void ldmx4(unsigned* a, unsigned saddr) {
    asm volatile("ldmatrix.sync.aligned.m8n8.x4.shared.b16 {%0,%1,%2,%3}, [%4];"
                 : "=r"(a[0]), "=r"(a[1]), "=r"(a[2]), "=r"(a[3]) : "r"(saddr));
}
__device__ __forceinline__ void ldmx2(unsigned* a, unsigned saddr) {
    asm volatile("ldmatrix.sync.aligned.m8n8.x2.shared.b16 {%0,%1}, [%2];"
                 : "=r"(a[0]), "=r"(a[1]) : "r"(saddr));
}
__device__ __forceinline__ void mma16816(float* d, const unsigned* a, unsigned b0, unsigned b1) {
    asm volatile(
        "mma.sync.aligned.m16n8k16.row.col.f32.bf16.bf16.f32 "
        "{%0,%1,%2,%3},{%4,%5,%6,%7},{%8,%9},{%0,%1,%2,%3};"
        : "+f"(d[0]), "+f"(d[1]), "+f"(d[2]), "+f"(d[3])
        : "r"(a[0]), "r"(a[1]), "r"(a[2]), "r"(a[3]), "r"(b0), "r"(b1));
}

// ---------------------------------------------------------------------------
// Kernel 1: convert Vt fp32 -> bf16
// ---------------------------------------------------------------------------
__global__ void convert_kernel(const float* __restrict__ Vt) {
    size_t t = (size_t)blockIdx.x * 256 + threadIdx.x;
    const float4* src = (const float4*)Vt;
    const size_t stride = 1728ull * 256ull;
    #pragma unroll 16
    for (int j = 0; j < 16; j++) {
        size_t i = t + stride * j;
        float4 v = src[i];
        __nv_bfloat162 lo, hi;
        lo.x = __float2bfloat16_rn(v.x); lo.y = __float2bfloat16_rn(v.y);
        hi.x = __float2bfloat16_rn(v.z); hi.y = __float2bfloat16_rn(v.w);
        uint2 pk; pk.x = *(const unsigned*)&lo; pk.y = *(const unsigned*)&hi;
        *(uint2*)(g_Vbf + 4 * i) = pk;
    }
}

// W^T bf16: g_WTbf[h][y] = W[y][h]; rows >= 192 zero
__global__ void convertWT_kernel(const float* __restrict__ W) {
    int h = blockIdx.x;
    for (int y = threadIdx.x; y < X384; y += blockDim.x)
        g_WTbf[h * X384 + y] = __float2bfloat16_rn(h < H ? W[y * H + h] : 0.f);
}

// ---------------------------------------------------------------------------
// Kernel 2: leaf embedding gather + level-0 B production
// leaf L = bt*32 + q (bt tree, q leaf-in-tree) is child (q&1) of
// level-0 B row m = bt*16 + q/2.
// ---------------------------------------------------------------------------
__global__ void leaf_kernel(const float* __restrict__ embed, const int* __restrict__ leaf_ids) {
    int n = blockIdx.x, t = threadIdx.x;
    float v = embed[(size_t)leaf_ids[n] * H + t];
    g_nodes[n * H + t] = v;
    int q = n & 31;
    int m = (n >> 5) * 16 + (q >> 1);
    g_cB[m * X384 + (q & 1) * H + t] = __float2bfloat16_rn(v);
}

// ---------------------------------------------------------------------------
// Level GEMM, M=64 row blocks, XOR-swizzled smem (no padding), 3 CTAs/SM.
//   mblk < 1152 : A = V rows (h = mblk/6, x-block = mblk%6) -> U[x,n],
//                 epilogue y[n] += sum_x c[n,x] U[x,n] -> g_part[xb][h][n]
//   mblk >=1152 : A = W^T rows (64 per block) -> g_part[6][h][n]
// A smem stage: 64 rows x 64 cols bf16 (128B rows, chunk XOR swizzle).
// B smem: NTILE rows x 384 cols bf16 (768B rows, chunk XOR swizzle),
//         loaded via cp.async in the SAME commit group as matching A stage.
// grid = (1156, ceil(Nlev/NTILE)), 256 threads (4 m-warps x 2 n-warps).
// ---------------------------------------------------------------------------
template <int NTILE>
__global__ void __launch_bounds__(256)
gemm_level() {
    constexpr int NT = NTILE / 16;               // n8 tiles per n-warp (4, 2, 1)
    constexpr int NP = NT / 2;                   // ldmatrix.x4 pairs (0 when NT==1)
    constexpr int NBCH = NTILE * 8;              // B chunks per stage

    extern __shared__ char smraw[];
    char* As = smraw;                            // [3][64][128B]
    char* Bp = smraw + 3 * 8192;                 // [NTILE][768B]
    float* ysm = (float*)(Bp + NTILE * 768);     // [4][NTILE]

    const int mblk = blockIdx.x;
    const int n0 = blockIdx.y * NTILE;
    const bool isW = (mblk >= 1152);
    const __nv_bfloat16* __restrict__ Ag = isW
        ? (g_WTbf + (size_t)(mblk - 1152) * 64 * X384)
        : (g_Vbf + ((size_t)(mblk / 6) * X384 + (mblk % 6) * 64) * X384);

    const int tid = threadIdx.x;
    const int ar = tid >> 3, ac = tid & 7;       // A: rows {ar, ar+32}, chunk ac

    // ---- prologue: stages 0,1 (A + B k-slice in one group each) ----
    #pragma unroll
    for (int s = 0; s < 2; s++) {
        char* Ad = As + s * 8192;
        #pragma unroll
        for (int t = 0; t < 2; t++) {
            int r = ar + t * 32;
            cp16(Ad + r * 128 + (((ac ^ (r & 7)) << 4)), Ag + r * X384 + s * 64 + ac * 8);
        }
        for (int j = tid; j < NBCH; j += 256) {
            int n = j >> 3, c = j & 7;
            cp16(Bp + n * 768 + ((((s * 8 + c) ^ (n & 7)) << 4)),
                 g_cB + (size_t)(n0 + n) * X384 + s * 64 + c * 8);
        }
        cp_commit();
    }

    const int warp = tid >> 5, lane = tid & 31;
    const int wm = warp & 3, wn = warp >> 2;     // 4 m-warps x 2 n-warps
    const int g = lane >> 2, tg = lane & 3;
    const int m0 = wm * 16;
    const int nb0 = wn * (NT * 8);

    const unsigned As_u = (unsigned)__cvta_generic_to_shared(As);
    const unsigned Bs_u = (unsigned)__cvta_generic_to_shared(Bp);

    // A ldmatrix addresses (stage-relative, one per k-step)
    const int am = m0 + (lane & 15);
    unsigned a_off[4];
    #pragma unroll
    for (int ks = 0; ks < 4; ks++) {
        int c = ks * 2 + (lane >> 4);
        a_off[ks] = (unsigned)(am * 128 + ((c ^ (am & 7)) << 4));
    }

    // B ldmatrix lane geometry
    const int bmm = lane >> 3, brr = lane & 7;
    const int rowo = (bmm & 2) ? 8 : 0, kos = bmm & 1;
    unsigned b_row[NP > 0 ? NP : 1];
    unsigned b_xm[NP > 0 ? NP : 1];
    #pragma unroll
    for (int p = 0; p < (NP > 0 ? NP : 1); p++) {
        int nr = nb0 + p * 16 + rowo + brr;
        b_row[p] = (unsigned)(nr * 768);
        b_xm[p] = (unsigned)(nr & 7);
    }
    const int nr1 = nb0 + brr;                   // NT==1 (x2) path
    const unsigned b_row1 = (unsigned)(nr1 * 768), b_xm1 = (unsigned)(nr1 & 7);

    float acc[NT][4];
    #pragma unroll
    for (int nt = 0; nt < NT; nt++)
        #pragma unroll
        for (int q = 0; q < 4; q++) acc[nt][q] = 0.f;

    // ---- mainloop over 6 k-stages ----
    for (int s = 0; s < NSUB; s++) {
        if (s == NSUB - 1) cp_wait<0>(); else cp_wait<1>();
        __syncthreads();
        int sn = s + 2;
        if (sn < NSUB) {                          // refill buffer freed by stage s-1
            char* Ad = As + (sn % 3) * 8192;
            #pragma unroll
            for (int t = 0; t < 2; t++) {
                int r = ar + t * 32;
                cp16(Ad + r * 128 + (((ac ^ (r & 7)) << 4)), Ag + r * X384 + sn * 64 + ac * 8);
            }
            for (int j = tid; j < NBCH; j += 256) {
                int n = j >> 3, c = j & 7;
                cp16(Bp + n * 768 + ((((sn * 8 + c) ^ (n & 7)) << 4)),
                     g_cB + (size_t)(n0 + n) * X384 + sn * 64 + c * 8);
            }
            cp_commit();
        }

        const unsigned a_stg = As_u + (s % 3) * 8192;
        const unsigned cb = (unsigned)(s * 8 + kos);

        #pragma unroll
        for (int ks = 0; ks < 4; ks++) {
            unsigned a[4];
            ldmx4(a, a_stg + a_off[ks]);
            if constexpr (NP > 0) {
                #pragma unroll
                for (int p = 0; p < NP; p++) {
                    unsigned bb[4];
                    unsigned c = cb + ks * 2;
                    ldmx4(bb, Bs_u + b_row[p] + ((c ^ b_xm[p]) << 4));
                    mma16816(acc[2 * p],     a, bb[0], bb[1]);
                    mma16816(acc[2 * p + 1], a, bb[2], bb[3]);
                }
            } else {
                unsigned bb[2];
                unsigned c = cb + ks * 2;
                ldmx2(bb, Bs_u + b_row1 + ((c ^ b_xm1) << 4));
                mma16816(acc[0], a, bb[0], bb[1]);
            }
        }
    }

    if (!isW) {
        const int xb = mblk % 6, hh = mblk / 6;
        #pragma unroll
        for (int nt = 0; nt < NT; nt++) {
            int nl = nb0 + nt * 8 + 2 * tg;       // local n (Bs row)
            // c[n, xf] from swizzled B smem
            int xf = xb * 64 + m0 + g;            // global x for this thread's rows
            auto bld = [&](int n, int col) -> float {
                unsigned off = (unsigned)(n * 768 + (((col >> 3) ^ (n & 7)) << 4) + ((col & 7) << 1));
                return __bfloat162float(*(const __nv_bfloat16*)(Bp + off));
            };
            float p0 = bld(nl, xf)     * acc[nt][0] + bld(nl, xf + 8)     * acc[nt][2];
            float p1 = bld(nl + 1, xf) * acc[nt][1] + bld(nl + 1, xf + 8) * acc[nt][3];
            #pragma unroll
            for (int sh = 4; sh < 32; sh <<= 1) { // reduce over g
                p0 += __shfl_xor_sync(0xffffffffu, p0, sh);
                p1 += __shfl_xor_sync(0xffffffffu, p1, sh);
            }
            if (g == 0) {
                ysm[wm * NTILE + nl] = p0;
                ysm[wm * NTILE + nl + 1] = p1;
            }
        }
        __syncthreads();
        for (int n = tid; n < NTILE; n += 256) {
            float v = ysm[n] + ysm[NTILE + n] + ysm[2 * NTILE + n] + ysm[3 * NTILE + n];
            g_part[xb][hh][n0 + n] = v;
        }
    } else {
        const int hb = (mblk - 1152) * 64;
        int hh = hb + m0 + g;
        #pragma unroll
        for (int nt = 0; nt < NT; nt++) {
            int n = n0 + nb0 + nt * 8 + 2 * tg;
            if (hh < H) {
                g_part[6][hh][n]     = acc[nt][0];
                g_part[6][hh][n + 1] = acc[nt][1];
            }
            if (hh + 8 < H) {
                g_part[6][hh + 8][n]     = acc[nt][2];
                g_part[6][hh + 8][n + 1] = acc[nt][3];
            }
        }
    }
}

// ---------------------------------------------------------------------------
// Finalize: sum partials + bias, tanh, write node + next level's B row.
// Output node n (of Nout, npt = Nout/8 per tree) is child (j&1) of next-level
// B row m = bt*(npt/2) + j/2 where bt = n/npt, j = n%npt.
// ---------------------------------------------------------------------------
__global__ void finalize_kernel(int outBase, int Nout, int hasNext,
                                const float* __restrict__ bias) {
    int n = blockIdx.x, h = threadIdx.x;
    float v = bias[h];
    #pragma unroll
    for (int i = 0; i < 7; i++) v += g_part[i][h][n];
    v = tanhf(v);
    g_nodes[(size_t)(outBase + n) * H + h] = v;
    if (hasNext) {
        int npt = Nout >> 3;
        int bt = n / npt, j = n - bt * npt;
        int m = bt * (npt >> 1) + (j >> 1);
        g_cB[m * X384 + (j & 1) * H + h] = __float2bfloat16_rn(v);
    }
}

// ---------------------------------------------------------------------------
// Logits + log_softmax, one warp per node
// ---------------------------------------------------------------------------
__global__ void logits_kernel(const float* __restrict__ Wout_w,
                              const float* __restrict__ Wout_b,
                              float* __restrict__ out) {
    int node = (blockIdx.x * blockDim.x + threadIdx.x) >> 5;   // 63 * 8 = 504
    int lane = threadIdx.x & 31;
    const float* v = g_nodes + (size_t)node * H;
    float l[5];
    #pragma unroll
    for (int o = 0; o < 5; o++) {
        float p = 0.f;
        #pragma unroll
        for (int i = 0; i < 6; i++) {
            int idx = lane + 32 * i;
            p += v[idx] * Wout_w[o * H + idx];
        }
        #pragma unroll
        for (int s = 16; s; s >>= 1) p += __shfl_xor_sync(0xffffffffu, p, s);
        l[o] = p + Wout_b[o];
    }
    if (lane == 0) {
        float m = l[0];
        #pragma unroll
        for (int o = 1; o < 5; o++) m = fmaxf(m, l[o]);
        float s = 0.f;
        #pragma unroll
        for (int o = 0; o < 5; o++) s += expf(l[o] - m);
        float ls = logf(s);
        #pragma unroll
        for (int o = 0; o < 5; o++) out[node * 5 + o] = l[o] - m - ls;
    }
}

// ---------------------------------------------------------------------------
static inline size_t smem_bytes(int NTILE) {
    return (size_t)3 * 8192 + (size_t)NTILE * 768 + (size_t)4 * NTILE * 4;
}

extern "C" void kernel_launch(void* const* d_in, const int* in_sizes, int n_in,
                              void* d_out, int out_size) {
    const float* embed  = (const float*)d_in[0];
    const float* Vt     = (const float*)d_in[1];
    const float* W      = (const float*)d_in[2];
    const float* b      = (const float*)d_in[3];
    const float* Wout_w = (const float*)d_in[4];
    const float* Wout_b = (const float*)d_in[5];
    const int*   leaf   = (const int*)d_in[6];
    float* out = (float*)d_out;

    static bool attr_set = false;
    if (!attr_set) {
        cudaFuncSetAttribute(gemm_level<64>, cudaFuncAttributeMaxDynamicSharedMemorySize, (int)smem_bytes(64));
        cudaFuncSetAttribute(gemm_level<32>, cudaFuncAttributeMaxDynamicSharedMemorySize, (int)smem_bytes(32));
        cudaFuncSetAttribute(gemm_level<16>, cudaFuncAttributeMaxDynamicSharedMemorySize, (int)smem_bytes(16));
        attr_set = true;
    }

    convert_kernel<<<1728, 256>>>(Vt);
    convertWT_kernel<<<256, 128>>>(W);
    leaf_kernel<<<256, H>>>(embed, leaf);   // also builds level-0 B

    // level 0: 256 leaves -> 128 nodes
    gemm_level<64><<<dim3(1156, 2), 256, smem_bytes(64)>>>();
    finalize_kernel<<<128, H>>>(256, 128, 1, b);
    // level 1: 128 -> 64
    gemm_level<64><<<dim3(1156, 1), 256, smem_bytes(64)>>>();
    finalize_kernel<<<64, H>>>(384, 64, 1, b);
    // level 2: 64 -> 32
    gemm_level<32><<<dim3(1156, 1), 256, smem_bytes(32)>>>();
    finalize_kernel<<<32, H>>>(448, 32, 1, b);
    // level 3: 32 -> 16
    gemm_level<16><<<dim3(1156, 1), 256, smem_bytes(16)>>>();
    finalize_kernel<<<16, H>>>(480, 16, 1, b);
    // level 4: 16 -> 8 (B rows 8..15 stale but feed only unused columns)
    gemm_level<16><<<dim3(1156, 1), 256, smem_bytes(16)>>>();
    finalize_kernel<<<8, H>>>(496, 8, 0, b);

    logits_kernel<<<63, 256>>>(Wout_w, Wout_b, out);
}